// round 13
// baseline (speedup 1.0000x reference)
#include <cuda_runtime.h>
#include <cuda_fp16.h>
#include <math.h>

#define H 128
#define G 50
#define NBINS 4096
#define CUTOFF_F 10.0f
#define NMAX 10000
#define EMAX 320000
#define LMAX 6
#define PI_F 3.14159265358979323846f

__device__ __align__(16) float  g_h[NMAX * H];
__device__ __align__(16) __half g_xfh[NMAX * H];
__device__ __align__(16) __half g_aggh[NMAX * H];
__device__ __align__(16) __half g_tab[LMAX * (NBINS + 1) * H];
__device__ float g_acc[64];
__device__ int  g_rowptr[NMAX + 1];
__device__ int  g_rank[EMAX];
__device__ __align__(16) int2 g_csr[EMAX];
__device__ __align__(16) __half g_w1t[LMAX * H * H];
__device__ __align__(16) __half g_w2t[LMAX * H * H];
__device__ __align__(16) __half g_w3t[LMAX * H * H];
__device__ __align__(16) __half g_o1t[64 * H];

__device__ __forceinline__ float sspf(float x) {
    return fmaxf(x, 0.f) + log1pf(expf(-fabsf(x))) - 0.69314718055994530942f;
}

// ---- f32x2 helpers (table build) ----
__device__ __forceinline__ void fma2(unsigned long long& d, unsigned long long a, unsigned long long b) {
    asm("fma.rn.f32x2 %0, %1, %2, %0;" : "+l"(d) : "l"(a), "l"(b));
}
__device__ __forceinline__ unsigned long long bcast2(float a) {
    unsigned long long r; asm("mov.b64 %0, {%1, %1};" : "=l"(r) : "f"(a)); return r;
}
__device__ __forceinline__ unsigned long long pack2(float a, float b) {
    unsigned long long r; asm("mov.b64 %0, {%1, %2};" : "=l"(r) : "f"(a), "f"(b)); return r;
}
__device__ __forceinline__ float2 unpack2(unsigned long long v) {
    float2 f; asm("mov.b64 {%0, %1}, %2;" : "=f"(f.x), "=f"(f.y) : "l"(v)); return f;
}

// ---- HMMA m16n8k16 ----
__device__ __forceinline__ void hmma16816(float& c0, float& c1, float& c2, float& c3,
                                          unsigned a0, unsigned a1, unsigned a2, unsigned a3,
                                          unsigned b0, unsigned b1) {
    asm volatile(
        "mma.sync.aligned.m16n8k16.row.col.f32.f16.f16.f32 "
        "{%0,%1,%2,%3}, {%4,%5,%6,%7}, {%8,%9}, {%0,%1,%2,%3};"
        : "+f"(c0), "+f"(c1), "+f"(c2), "+f"(c3)
        : "r"(a0), "r"(a1), "r"(a2), "r"(a3), "r"(b0), "r"(b1));
}

__global__ void convert_weights(const float* __restrict__ w1, const float* __restrict__ w2,
                                const float* __restrict__ w3, const float* __restrict__ o1w, int L) {
    int total = L * H * H;
    for (int idx = blockIdx.x * blockDim.x + threadIdx.x; idx < total; idx += gridDim.x * blockDim.x) {
        int l = idx >> 14;
        int r = idx & 16383;
        int k = r >> 7, n = r & 127;
        int o = (l << 14) + (n << 7) + k;
        g_w1t[o] = __float2half(w1[idx]);
        g_w2t[o] = __float2half(w2[idx]);
        g_w3t[o] = __float2half(w3[idx]);
    }
    for (int idx = blockIdx.x * blockDim.x + threadIdx.x; idx < H * 64; idx += gridDim.x * blockDim.x) {
        int k = idx >> 6, n = idx & 63;
        g_o1t[n * H + k] = __float2half(o1w[idx]);
    }
}

__global__ void embed_kernel(const int* __restrict__ x, const float* __restrict__ emb, int N) {
    int n = blockIdx.x;
    if (n < N) g_h[n * H + threadIdx.x] = emb[x[n] * H + threadIdx.x];
}

// ======================= CSR build =======================
__global__ void hist_kernel(const int* __restrict__ dst, int E) {
    int e = blockIdx.x * blockDim.x + threadIdx.x;
    if (e < E) g_rank[e] = atomicAdd(&g_rowptr[dst[e] + 1], 1);
}

__global__ void __launch_bounds__(1024) scan_kernel(int n) {
    __shared__ int buf[10240];
    __shared__ int wsum[32];
    int t = threadIdx.x;
    const int C = 10;
    for (int i = t; i < 10240; i += 1024) buf[i] = (i < n) ? g_rowptr[i] : 0;
    __syncthreads();
    int base = t * C;
    int s = 0;
#pragma unroll
    for (int i = 0; i < C; i++) s += buf[base + i];
    int lane = t & 31, w = t >> 5;
    int v = s;
#pragma unroll
    for (int off = 1; off < 32; off <<= 1) {
        int u = __shfl_up_sync(0xffffffffu, v, off);
        if (lane >= off) v += u;
    }
    if (lane == 31) wsum[w] = v;
    __syncthreads();
    if (w == 0) {
        int xv = wsum[lane];
#pragma unroll
        for (int off = 1; off < 32; off <<= 1) {
            int u = __shfl_up_sync(0xffffffffu, xv, off);
            if (lane >= off) xv += u;
        }
        wsum[lane] = xv;
    }
    __syncthreads();
    int run = v - s + (w > 0 ? wsum[w - 1] : 0);
#pragma unroll
    for (int i = 0; i < C; i++) { run += buf[base + i]; buf[base + i] = run; }
    __syncthreads();
    for (int i = t; i < n; i += 1024) g_rowptr[i] = buf[i];
}

__global__ void scatter_kernel(const int* __restrict__ src, const int* __restrict__ dst,
                               const float* __restrict__ dist, int E) {
    int e = blockIdx.x * blockDim.x + threadIdx.x;
    if (e < E) {
        int p = g_rowptr[dst[e]] + g_rank[e];
        g_csr[p] = make_int2(src[e], __float_as_int(dist[e]));
    }
}

// ======================= Filter tables (all layers, one launch) ====
// 2 bins per block; nearest-neighbor table (no lerp pairs).
__global__ void __launch_bounds__(128) table_all(
    const float* __restrict__ mw1, const float* __restrict__ mb1,
    const float* __restrict__ mw2, const float* __restrict__ mb2)
{
    __shared__ float a_s[2][H];
    __shared__ float eas[2][G];
    int f = threadIdx.x;
    int b0 = blockIdx.x * 2;
    int l = blockIdx.y;
    const float* w1 = mw1 + (size_t)l * G * H;
    const float* b1 = mb1 + (size_t)l * H;
    const float* w2 = mw2 + (size_t)l * H * H;
    const float* b2 = mb2 + (size_t)l * H;
    __half* tab = g_tab + (size_t)l * (NBINS + 1) * H;
    const float spacing = CUTOFF_F / (G - 1);
    const float coeff = -0.5f / (spacing * spacing);
    if (f < 2 * G) {
        int bi = f / G, g = f - bi * G;
        float d = (b0 + bi) * (CUTOFF_F / NBINS);
        float dd = d - g * spacing;
        eas[bi][g] = expf(coeff * dd * dd);
    }
    __syncthreads();
    float bv = b1[f];
    float a0 = bv, a1 = bv;
#pragma unroll
    for (int g = 0; g < G; g++) {
        float w = w1[g * H + f];
        a0 += eas[0][g] * w;
        a1 += eas[1][g] * w;
    }
    a_s[0][f] = sspf(a0);
    a_s[1][f] = sspf(a1);
    __syncthreads();
    unsigned long long acc01 = 0ull;
#pragma unroll 8
    for (int j = 0; j < H; j++) {
        float w = w2[j * H + f];
        fma2(acc01, pack2(a_s[0][j], a_s[1][j]), bcast2(w));
    }
    float2 v01 = unpack2(acc01);
    float b2v = b2[f];
    float v0 = v01.x + b2v, v1 = v01.y + b2v;
    float d0 = b0 * (CUTOFF_F / NBINS);
    float d1 = (b0 + 1) * (CUTOFF_F / NBINS);
    v0 *= 0.5f * (cosf(d0 * (PI_F / CUTOFF_F)) + 1.f);
    v1 *= 0.5f * (cosf(d1 * (PI_F / CUTOFF_F)) + 1.f);
    if (b0 <= NBINS)     tab[(size_t)b0 * H + f] = __float2half(v0);
    if (b0 + 1 <= NBINS) tab[(size_t)(b0 + 1) * H + f] = __float2half(v1);
}

// ======================= HMMA common (32-row tiles) =======================
#define APAD 136

__device__ __forceinline__ void stage_A32(const float* __restrict__ A, __half (*As)[APAD],
                                          int r0, int M, int tid) {
#pragma unroll
    for (int rep = 0; rep < 4; rep++) {
        int fl = tid + rep * 256;
        int row = fl >> 5, f4 = fl & 31;
        float4 v = (r0 + row < M) ? *(const float4*)&A[(size_t)(r0 + row) * H + f4 * 4]
                                  : make_float4(0.f, 0.f, 0.f, 0.f);
        __half2* p = (__half2*)&As[row][f4 * 4];
        p[0] = __floats2half2_rn(v.x, v.y);
        p[1] = __floats2half2_rn(v.z, v.w);
    }
}

// fp16 copy stage, 32 rows
__device__ __forceinline__ void stage_Ah32(const __half* __restrict__ A, __half (*As)[APAD],
                                           int r0, int M, int tid) {
#pragma unroll
    for (int rep = 0; rep < 2; rep++) {
        int fl = tid + rep * 256;
        int row = fl >> 4, u4 = fl & 15;
        uint4 v = (r0 + row < M) ? *(const uint4*)&A[(size_t)(r0 + row) * H + u4 * 8]
                                 : make_uint4(0u, 0u, 0u, 0u);
        *(uint4*)&As[row][u4 * 8] = v;
    }
}

__device__ __forceinline__ void stage_W(const __half* __restrict__ Wt, __half (*Ws)[APAD], int tid) {
#pragma unroll
    for (int rep = 0; rep < 8; rep++) {
        int w = tid + rep * 256;
        int n = w >> 4, kg = w & 15;
        *(uint4*)&Ws[n][kg * 8] = *(const uint4*)&Wt[n * H + kg * 8];
    }
}

__device__ __forceinline__ void stage_W64(const __half* __restrict__ Wt, __half (*Ws)[APAD], int tid) {
#pragma unroll
    for (int rep = 0; rep < 4; rep++) {
        int w = tid + rep * 256;
        int n = w >> 4, kg = w & 15;
        *(uint4*)&Ws[n][kg * 8] = *(const uint4*)&Wt[n * H + kg * 8];
    }
}

__device__ __forceinline__ void hmma32(const __half (*As)[APAD], const __half (*Ws)[APAD],
                                       float (&acc)[4][4], int warp_m, int warp_n,
                                       int tm, int tk) {
#pragma unroll
    for (int kc = 0; kc < 8; kc++) {
        int k0 = kc * 16;
        int mrow = warp_m * 16 + tm;
        unsigned a0 = *(const unsigned*)&As[mrow][k0 + tk];
        unsigned a1 = *(const unsigned*)&As[mrow + 8][k0 + tk];
        unsigned a2 = *(const unsigned*)&As[mrow][k0 + 8 + tk];
        unsigned a3 = *(const unsigned*)&As[mrow + 8][k0 + 8 + tk];
#pragma unroll
        for (int nt = 0; nt < 4; nt++) {
            int n0 = warp_n * 32 + nt * 8;
            unsigned b0 = *(const unsigned*)&Ws[n0 + tm][k0 + tk];
            unsigned b1 = *(const unsigned*)&Ws[n0 + tm][k0 + 8 + tk];
            hmma16816(acc[nt][0], acc[nt][1], acc[nt][2], acc[nt][3], a0, a1, a2, a3, b0, b1);
        }
    }
}

__device__ __forceinline__ void zero4(float (&acc)[4][4]) {
#pragma unroll
    for (int nt = 0; nt < 4; nt++)
#pragma unroll
        for (int i = 0; i < 4; i++) acc[nt][i] = 0.f;
}

// xf(fp16) = h(fp32) @ W  (layer 0)
__global__ void __launch_bounds__(256) gemm_xf(const float* __restrict__ A,
                                               const __half* __restrict__ Wt,
                                               __half* __restrict__ out, int M) {
    __shared__ __half As[32][APAD];
    __shared__ __half Ws[128][APAD];
    int tid = threadIdx.x;
    int warp = tid >> 5, lane = tid & 31;
    int warp_m = warp >> 2, warp_n = warp & 3;
    int tm = lane >> 2, tk = (lane & 3) * 2;
    int r0 = blockIdx.x * 32;
    stage_A32(A, As, r0, M, tid);
    stage_W(Wt, Ws, tid);
    __syncthreads();
    float acc[4][4];
    zero4(acc);
    hmma32(As, Ws, acc, warp_m, warp_n, tm, tk);
    int row1 = r0 + warp_m * 16 + tm;
    int row2 = row1 + 8;
#pragma unroll
    for (int nt = 0; nt < 4; nt++) {
        int col = warp_n * 32 + nt * 8 + tk;
        if (row1 < M) *(__half2*)&out[(size_t)row1 * H + col] = __floats2half2_rn(acc[nt][0], acc[nt][1]);
        if (row2 < M) *(__half2*)&out[(size_t)row2 * H + col] = __floats2half2_rn(acc[nt][2], acc[nt][3]);
    }
}

// ======================= Edge gather (nearest-bin table) ======
__global__ void edge_gather(const __half* __restrict__ tab, int N) {
    int warp = (blockIdx.x * blockDim.x + threadIdx.x) >> 5;
    int lane = threadIdx.x & 31;
    if (warp >= N) return;
    int beg = g_rowptr[warp], end = g_rowptr[warp + 1];
    float a0 = 0.f, a1 = 0.f, a2 = 0.f, a3 = 0.f;
#pragma unroll 4
    for (int i = beg; i < end; i++) {
        int2 sd = g_csr[i];
        float d = __int_as_float(sd.y);
        float u = d * ((float)NBINS / CUTOFF_F) + 0.5f;
        int i0 = min(max((int)u, 0), NBINS);
        uint2 tp = *(const uint2*)&tab[(size_t)i0 * H + lane * 4];
        uint2 xq = *(const uint2*)&g_xfh[(size_t)sd.x * H + lane * 4];
        float2 w0 = __half22float2(*(__half2*)&tp.x);
        float2 w1 = __half22float2(*(__half2*)&tp.y);
        float2 xa = __half22float2(*(__half2*)&xq.x);
        float2 xb = __half22float2(*(__half2*)&xq.y);
        a0 += xa.x * w0.x;
        a1 += xa.y * w0.y;
        a2 += xb.x * w1.x;
        a3 += xb.y * w1.y;
    }
    __half2* op = (__half2*)&g_aggh[(size_t)warp * H + lane * 4];
    op[0] = __floats2half2_rn(a0, a1);
    op[1] = __floats2half2_rn(a2, a3);
}

// h += ssp(aggh @ W2 + b2) @ W3 + b3;  then xf_next = h_new @ W1n
__global__ void __launch_bounds__(256) gemm_dualX(const __half* __restrict__ A,
                                                  const __half* __restrict__ W2t,
                                                  const float* __restrict__ b2,
                                                  const __half* __restrict__ W3t,
                                                  const float* __restrict__ b3,
                                                  float* __restrict__ hio,
                                                  const __half* __restrict__ W1n,
                                                  __half* __restrict__ xfo, int M) {
    __shared__ __half As[32][APAD];
    __shared__ __half Ws[128][APAD];
    int tid = threadIdx.x;
    int warp = tid >> 5, lane = tid & 31;
    int warp_m = warp >> 2, warp_n = warp & 3;
    int tm = lane >> 2, tk = (lane & 3) * 2;
    int r0 = blockIdx.x * 32;
    int lr1 = warp_m * 16 + tm, lr2 = lr1 + 8;
    int row1 = r0 + lr1, row2 = r0 + lr2;

    stage_Ah32(A, As, r0, M, tid);
    stage_W(W2t, Ws, tid);
    __syncthreads();
    float acc[4][4];
    zero4(acc);
    hmma32(As, Ws, acc, warp_m, warp_n, tm, tk);
    __syncthreads();
#pragma unroll
    for (int nt = 0; nt < 4; nt++) {
        int col = warp_n * 32 + nt * 8 + tk;
        float2 bb = *(const float2*)&b2[col];
        *(__half2*)&As[lr1][col] = __floats2half2_rn(sspf(acc[nt][0] + bb.x), sspf(acc[nt][1] + bb.y));
        *(__half2*)&As[lr2][col] = __floats2half2_rn(sspf(acc[nt][2] + bb.x), sspf(acc[nt][3] + bb.y));
    }
    stage_W(W3t, Ws, tid);
    __syncthreads();
    zero4(acc);
    hmma32(As, Ws, acc, warp_m, warp_n, tm, tk);
    __syncthreads();
#pragma unroll
    for (int nt = 0; nt < 4; nt++) {
        int col = warp_n * 32 + nt * 8 + tk;
        float2 bb = *(const float2*)&b3[col];
        float2 o1 = make_float2(0.f, 0.f), o2 = make_float2(0.f, 0.f);
        if (row1 < M) o1 = *(const float2*)&hio[(size_t)row1 * H + col];
        if (row2 < M) o2 = *(const float2*)&hio[(size_t)row2 * H + col];
        o1.x += acc[nt][0] + bb.x; o1.y += acc[nt][1] + bb.y;
        o2.x += acc[nt][2] + bb.x; o2.y += acc[nt][3] + bb.y;
        if (row1 < M) *(float2*)&hio[(size_t)row1 * H + col] = o1;
        if (row2 < M) *(float2*)&hio[(size_t)row2 * H + col] = o2;
        *(__half2*)&As[lr1][col] = __floats2half2_rn(o1.x, o1.y);
        *(__half2*)&As[lr2][col] = __floats2half2_rn(o2.x, o2.y);
    }
    if (W1n) {
        stage_W(W1n, Ws, tid);
        __syncthreads();
        zero4(acc);
        hmma32(As, Ws, acc, warp_m, warp_n, tm, tk);
#pragma unroll
        for (int nt = 0; nt < 4; nt++) {
            int col = warp_n * 32 + nt * 8 + tk;
            if (row1 < M) *(__half2*)&xfo[(size_t)row1 * H + col] = __floats2half2_rn(acc[nt][0], acc[nt][1]);
            if (row2 < M) *(__half2*)&xfo[(size_t)row2 * H + col] = __floats2half2_rn(acc[nt][2], acc[nt][3]);
        }
    }
}

// ======================= Readout: colsum of ssp(h @ o1w + b1) via HMMA ====
__global__ void __launch_bounds__(256) readout_h(const float* __restrict__ A,
                                                 const float* __restrict__ b1, int M) {
    __shared__ __half As[64][APAD];
    __shared__ __half Ws[64][APAD];
    __shared__ float scol[64];
    int tid = threadIdx.x;
    int warp = tid >> 5, lane = tid & 31;
    int warp_m = warp >> 2, warp_n = warp & 3;
    int tm = lane >> 2, tk = (lane & 3) * 2;
    int r0 = blockIdx.x * 64;
    if (tid < 64) scol[tid] = 0.f;
#pragma unroll
    for (int rep = 0; rep < 8; rep++) {
        int fl = tid + rep * 256;
        int row = fl >> 5, f4 = fl & 31;
        float4 v = (r0 + row < M) ? *(const float4*)&A[(size_t)(r0 + row) * H + f4 * 4]
                                  : make_float4(0.f, 0.f, 0.f, 0.f);
        __half2* p = (__half2*)&As[row][f4 * 4];
        p[0] = __floats2half2_rn(v.x, v.y);
        p[1] = __floats2half2_rn(v.z, v.w);
    }
    stage_W64(g_o1t, Ws, tid);
    __syncthreads();
    float acc[2][2][4];
#pragma unroll
    for (int m = 0; m < 2; m++)
#pragma unroll
        for (int nt = 0; nt < 2; nt++)
#pragma unroll
            for (int i = 0; i < 4; i++) acc[m][nt][i] = 0.f;
#pragma unroll
    for (int msub = 0; msub < 2; msub++) {
        int mrow = msub * 32 + warp_m * 16 + tm;
#pragma unroll
        for (int kc = 0; kc < 8; kc++) {
            int k0 = kc * 16;
            unsigned a0 = *(const unsigned*)&As[mrow][k0 + tk];
            unsigned a1 = *(const unsigned*)&As[mrow + 8][k0 + tk];
            unsigned a2 = *(const unsigned*)&As[mrow][k0 + 8 + tk];
            unsigned a3 = *(const unsigned*)&As[mrow + 8][k0 + 8 + tk];
#pragma unroll
            for (int nt = 0; nt < 2; nt++) {
                int n0 = warp_n * 16 + nt * 8;
                unsigned b0 = *(const unsigned*)&Ws[n0 + tm][k0 + tk];
                unsigned bq1 = *(const unsigned*)&Ws[n0 + tm][k0 + 8 + tk];
                hmma16816(acc[msub][nt][0], acc[msub][nt][1], acc[msub][nt][2], acc[msub][nt][3],
                          a0, a1, a2, a3, b0, bq1);
            }
        }
    }
    float cs[2][2] = {{0.f, 0.f}, {0.f, 0.f}};
#pragma unroll
    for (int msub = 0; msub < 2; msub++) {
        int row1 = r0 + msub * 32 + warp_m * 16 + tm;
        int row2 = row1 + 8;
#pragma unroll
        for (int nt = 0; nt < 2; nt++) {
            int col = warp_n * 16 + nt * 8 + tk;
            float2 bb = *(const float2*)&b1[col];
            if (row1 < M) {
                cs[nt][0] += sspf(acc[msub][nt][0] + bb.x);
                cs[nt][1] += sspf(acc[msub][nt][1] + bb.y);
            }
            if (row2 < M) {
                cs[nt][0] += sspf(acc[msub][nt][2] + bb.x);
                cs[nt][1] += sspf(acc[msub][nt][3] + bb.y);
            }
        }
    }
#pragma unroll
    for (int off = 16; off >= 4; off >>= 1) {
#pragma unroll
        for (int nt = 0; nt < 2; nt++) {
            cs[nt][0] += __shfl_down_sync(0xffffffffu, cs[nt][0], off);
            cs[nt][1] += __shfl_down_sync(0xffffffffu, cs[nt][1], off);
        }
    }
    if (lane < 4) {
#pragma unroll
        for (int nt = 0; nt < 2; nt++) {
            int col = warp_n * 16 + nt * 8 + lane * 2;
            atomicAdd(&scol[col], cs[nt][0]);
            atomicAdd(&scol[col + 1], cs[nt][1]);
        }
    }
    __syncthreads();
    if (tid < 64) atomicAdd(&g_acc[tid], scol[tid]);
}

__global__ void readout_final(const float* __restrict__ o2w, const float* __restrict__ o2b,
                              const float* __restrict__ rw, const float* __restrict__ rb,
                              float* __restrict__ out, int N) {
    __shared__ float v[64];
    int t = threadIdx.x;
    float a = (float)N * o2b[t];
#pragma unroll 8
    for (int j = 0; j < 64; j++) a += g_acc[j] * o2w[j * 64 + t];
    v[t] = a;
    __syncthreads();
    if (t < 12) {
        float r = rb[t];
#pragma unroll
        for (int j = 0; j < 64; j++) r += v[j] * rw[j * 12 + t];
        out[t] = r;
    }
}

extern "C" void kernel_launch(void* const* d_in, const int* in_sizes, int n_in,
                              void* d_out, int out_size) {
    const int*   x    = (const int*)d_in[0];
    const int*   ei   = (const int*)d_in[1];
    const float* dist = (const float*)d_in[2];
    const float* emb  = (const float*)d_in[3];
    const float* mw1  = (const float*)d_in[4];
    const float* mb1  = (const float*)d_in[5];
    const float* mw2  = (const float*)d_in[6];
    const float* mb2  = (const float*)d_in[7];
    const float* l1w  = (const float*)d_in[8];
    const float* l2w  = (const float*)d_in[9];
    const float* l2b  = (const float*)d_in[10];
    const float* lw   = (const float*)d_in[11];
    const float* lb   = (const float*)d_in[12];
    const float* o1w  = (const float*)d_in[13];
    const float* o1b  = (const float*)d_in[14];
    const float* o2w  = (const float*)d_in[15];
    const float* o2b  = (const float*)d_in[16];
    const float* rw   = (const float*)d_in[17];
    const float* rb   = (const float*)d_in[18];

    int N = in_sizes[0];
    int E = in_sizes[2];
    int L = in_sizes[4] / (G * H);

    float *pacc;
    int *prow;
    cudaGetSymbolAddress((void**)&pacc, g_acc);
    cudaGetSymbolAddress((void**)&prow, g_rowptr);
    float *ph;
    __half *pxfh, *paggh, *pw1t, *pw2t, *pw3t, *ptab;
    cudaGetSymbolAddress((void**)&ph, g_h);
    cudaGetSymbolAddress((void**)&pxfh, g_xfh);
    cudaGetSymbolAddress((void**)&paggh, g_aggh);
    cudaGetSymbolAddress((void**)&pw1t, g_w1t);
    cudaGetSymbolAddress((void**)&pw2t, g_w2t);
    cudaGetSymbolAddress((void**)&pw3t, g_w3t);
    cudaGetSymbolAddress((void**)&ptab, g_tab);

    const int* esrc = ei;
    const int* edst = ei + E;

    int nb32 = (N + 31) / 32;
    int nb64 = (N + 63) / 64;
    int nbE = (N + 7) / 8;

    embed_kernel<<<N, 128>>>(x, emb, N);
    cudaMemsetAsync(prow, 0, (N + 1) * sizeof(int));
    hist_kernel<<<(E + 255) / 256, 256>>>(edst, E);
    scan_kernel<<<1, 1024>>>(N + 1);
    scatter_kernel<<<(E + 255) / 256, 256>>>(esrc, edst, dist, E);
    convert_weights<<<256, 256>>>(l1w, l2w, lw, o1w, L);
    gemm_xf<<<nb32, 256>>>(ph, pw1t, pxfh, N);
    dim3 tgrid((NBINS + 2) / 2, L);
    table_all<<<tgrid, 128>>>(mw1, mb1, mw2, mb2);

    for (int l = 0; l < L; l++) {
        edge_gather<<<nbE, 256>>>(ptab + (size_t)l * (NBINS + 1) * H, N);
        const __half* w1n = (l + 1 < L) ? pw1t + (size_t)(l + 1) * H * H : nullptr;
        gemm_dualX<<<nb32, 256>>>(paggh, pw2t + (size_t)l * H * H, l2b + (size_t)l * H,
                                  pw3t + (size_t)l * H * H, lb + (size_t)l * H,
                                  ph, w1n, pxfh, N);
    }

    cudaMemsetAsync(pacc, 0, 64 * sizeof(float));
    readout_h<<<nb64, 256>>>(ph, o1b, N);
    readout_final<<<1, 64>>>(o2w, o2b, rw, rb, (float*)d_out, N);
}

// round 14
// speedup vs baseline: 1.2259x; 1.2259x over previous
#include <cuda_runtime.h>
#include <cuda_fp16.h>
#include <math.h>

#define H 128
#define G 50
#define NBINS 2048
#define BPB 16
#define CUTOFF_F 10.0f
#define NMAX 10000
#define EMAX 320000
#define LMAX 6
#define PI_F 3.14159265358979323846f

__device__ __align__(16) float  g_h[NMAX * H];
__device__ __align__(16) __half g_xfh[NMAX * H];
__device__ __align__(16) __half g_aggh[NMAX * H];
__device__ __align__(16) __half g_tab[LMAX * (NBINS + 1) * H];
__device__ float g_acc[64];
__device__ int  g_rowptr[NMAX + 1];
__device__ int  g_rank[EMAX];
__device__ __align__(16) int2 g_csr[EMAX];
__device__ __align__(16) __half g_w1t[LMAX * H * H];
__device__ __align__(16) __half g_w2t[LMAX * H * H];
__device__ __align__(16) __half g_w3t[LMAX * H * H];
__device__ __align__(16) __half g_o1t[64 * H];

__device__ __forceinline__ float sspf(float x) {
    return fmaxf(x, 0.f) + log1pf(expf(-fabsf(x))) - 0.69314718055994530942f;
}

// ---- f32x2 helpers (table build) ----
__device__ __forceinline__ void fma2(unsigned long long& d, unsigned long long a, unsigned long long b) {
    asm("fma.rn.f32x2 %0, %1, %2, %0;" : "+l"(d) : "l"(a), "l"(b));
}
__device__ __forceinline__ unsigned long long bcast2(float a) {
    unsigned long long r; asm("mov.b64 %0, {%1, %1};" : "=l"(r) : "f"(a)); return r;
}
__device__ __forceinline__ unsigned long long pack2(float a, float b) {
    unsigned long long r; asm("mov.b64 %0, {%1, %2};" : "=l"(r) : "f"(a), "f"(b)); return r;
}
__device__ __forceinline__ float2 unpack2(unsigned long long v) {
    float2 f; asm("mov.b64 {%0, %1}, %2;" : "=f"(f.x), "=f"(f.y) : "l"(v)); return f;
}

// ---- HMMA m16n8k16 ----
__device__ __forceinline__ void hmma16816(float& c0, float& c1, float& c2, float& c3,
                                          unsigned a0, unsigned a1, unsigned a2, unsigned a3,
                                          unsigned b0, unsigned b1) {
    asm volatile(
        "mma.sync.aligned.m16n8k16.row.col.f32.f16.f16.f32 "
        "{%0,%1,%2,%3}, {%4,%5,%6,%7}, {%8,%9}, {%0,%1,%2,%3};"
        : "+f"(c0), "+f"(c1), "+f"(c2), "+f"(c3)
        : "r"(a0), "r"(a1), "r"(a2), "r"(a3), "r"(b0), "r"(b1));
}

__global__ void convert_weights(const float* __restrict__ w1, const float* __restrict__ w2,
                                const float* __restrict__ w3, const float* __restrict__ o1w, int L) {
    int total = L * H * H;
    for (int idx = blockIdx.x * blockDim.x + threadIdx.x; idx < total; idx += gridDim.x * blockDim.x) {
        int l = idx >> 14;
        int r = idx & 16383;
        int k = r >> 7, n = r & 127;
        int o = (l << 14) + (n << 7) + k;
        g_w1t[o] = __float2half(w1[idx]);
        g_w2t[o] = __float2half(w2[idx]);
        g_w3t[o] = __float2half(w3[idx]);
    }
    for (int idx = blockIdx.x * blockDim.x + threadIdx.x; idx < H * 64; idx += gridDim.x * blockDim.x) {
        int k = idx >> 6, n = idx & 63;
        g_o1t[n * H + k] = __float2half(o1w[idx]);
    }
}

__global__ void embed_kernel(const int* __restrict__ x, const float* __restrict__ emb, int N) {
    int n = blockIdx.x;
    if (n < N) g_h[n * H + threadIdx.x] = emb[x[n] * H + threadIdx.x];
}

// ======================= CSR build =======================
__global__ void hist_kernel(const int* __restrict__ dst, int E) {
    int e = blockIdx.x * blockDim.x + threadIdx.x;
    if (e < E) g_rank[e] = atomicAdd(&g_rowptr[dst[e] + 1], 1);
}

__global__ void __launch_bounds__(1024) scan_kernel(int n) {
    __shared__ int buf[10240];
    __shared__ int wsum[32];
    int t = threadIdx.x;
    const int C = 10;
    for (int i = t; i < 10240; i += 1024) buf[i] = (i < n) ? g_rowptr[i] : 0;
    __syncthreads();
    int base = t * C;
    int s = 0;
#pragma unroll
    for (int i = 0; i < C; i++) s += buf[base + i];
    int lane = t & 31, w = t >> 5;
    int v = s;
#pragma unroll
    for (int off = 1; off < 32; off <<= 1) {
        int u = __shfl_up_sync(0xffffffffu, v, off);
        if (lane >= off) v += u;
    }
    if (lane == 31) wsum[w] = v;
    __syncthreads();
    if (w == 0) {
        int xv = wsum[lane];
#pragma unroll
        for (int off = 1; off < 32; off <<= 1) {
            int u = __shfl_up_sync(0xffffffffu, xv, off);
            if (lane >= off) xv += u;
        }
        wsum[lane] = xv;
    }
    __syncthreads();
    int run = v - s + (w > 0 ? wsum[w - 1] : 0);
#pragma unroll
    for (int i = 0; i < C; i++) { run += buf[base + i]; buf[base + i] = run; }
    __syncthreads();
    for (int i = t; i < n; i += 1024) g_rowptr[i] = buf[i];
}

__global__ void scatter_kernel(const int* __restrict__ src, const int* __restrict__ dst,
                               const float* __restrict__ dist, int E) {
    int e = blockIdx.x * blockDim.x + threadIdx.x;
    if (e < E) {
        int p = g_rowptr[dst[e]] + g_rank[e];
        g_csr[p] = make_int2(src[e], __float_as_int(dist[e]));
    }
}

// ======================= Filter tables: 16 bins/block, paired fma2 ====
__global__ void __launch_bounds__(128) table_all(
    const float* __restrict__ mw1, const float* __restrict__ mb1,
    const float* __restrict__ mw2, const float* __restrict__ mb2)
{
    __shared__ unsigned long long eas2[BPB / 2][G];   // (bin2p, bin2p+1) per gaussian
    __shared__ unsigned long long a_s2[BPB / 2][H];   // paired ssp(stage1) values
    int f = threadIdx.x;
    int b0 = blockIdx.x * BPB;
    int l = blockIdx.y;
    const float* w1 = mw1 + (size_t)l * G * H;
    const float* b1 = mb1 + (size_t)l * H;
    const float* w2 = mw2 + (size_t)l * H * H;
    const float* b2 = mb2 + (size_t)l * H;
    __half* tab = g_tab + (size_t)l * (NBINS + 1) * H;
    const float spacing = CUTOFF_F / (G - 1);
    const float coeff = -0.5f / (spacing * spacing);
    const float binw = CUTOFF_F / NBINS;

    for (int i = f; i < (BPB / 2) * G; i += 128) {
        int p = i / G, g = i - p * G;
        float dA = (b0 + 2 * p) * binw;
        float dB = dA + binw;
        float xA = dA - g * spacing, xB = dB - g * spacing;
        eas2[p][g] = pack2(expf(coeff * xA * xA), expf(coeff * xB * xB));
    }
    __syncthreads();

    // stage 1: a2[p] = b1 + sum_g eas2[p][g] * w1[g][f]   (paired over bins)
    unsigned long long a2[BPB / 2];
    {
        unsigned long long bvv = bcast2(b1[f]);
#pragma unroll
        for (int p = 0; p < BPB / 2; p++) a2[p] = bvv;
    }
#pragma unroll 2
    for (int g = 0; g < G; g++) {
        unsigned long long wb = bcast2(w1[g * H + f]);
#pragma unroll
        for (int p = 0; p < BPB / 2; p++) fma2(a2[p], eas2[p][g], wb);
    }
#pragma unroll
    for (int p = 0; p < BPB / 2; p++) {
        float2 v = unpack2(a2[p]);
        a_s2[p][f] = pack2(sspf(v.x), sspf(v.y));
    }
    __syncthreads();

    // stage 2: acc[p] = sum_j a_s2[p][j] * w2[j][f]
    unsigned long long acc[BPB / 2];
#pragma unroll
    for (int p = 0; p < BPB / 2; p++) acc[p] = 0ull;
#pragma unroll 4
    for (int j = 0; j < H; j++) {
        unsigned long long wb = bcast2(w2[j * H + f]);
#pragma unroll
        for (int p = 0; p < BPB / 2; p++) fma2(acc[p], a_s2[p][j], wb);
    }
    float b2v = b2[f];
#pragma unroll
    for (int p = 0; p < BPB / 2; p++) {
        float2 v = unpack2(acc[p]);
        int bA = b0 + 2 * p, bB = bA + 1;
        float cA = 0.5f * (cosf(bA * binw * (PI_F / CUTOFF_F)) + 1.f);
        float cB = 0.5f * (cosf(bB * binw * (PI_F / CUTOFF_F)) + 1.f);
        if (bA <= NBINS) tab[(size_t)bA * H + f] = __float2half((v.x + b2v) * cA);
        if (bB <= NBINS) tab[(size_t)bB * H + f] = __float2half((v.y + b2v) * cB);
    }
}

// ======================= HMMA common (32-row tiles) =======================
#define APAD 136

__device__ __forceinline__ void stage_A32(const float* __restrict__ A, __half (*As)[APAD],
                                          int r0, int M, int tid) {
#pragma unroll
    for (int rep = 0; rep < 4; rep++) {
        int fl = tid + rep * 256;
        int row = fl >> 5, f4 = fl & 31;
        float4 v = (r0 + row < M) ? *(const float4*)&A[(size_t)(r0 + row) * H + f4 * 4]
                                  : make_float4(0.f, 0.f, 0.f, 0.f);
        __half2* p = (__half2*)&As[row][f4 * 4];
        p[0] = __floats2half2_rn(v.x, v.y);
        p[1] = __floats2half2_rn(v.z, v.w);
    }
}

__device__ __forceinline__ void stage_Ah32(const __half* __restrict__ A, __half (*As)[APAD],
                                           int r0, int M, int tid) {
#pragma unroll
    for (int rep = 0; rep < 2; rep++) {
        int fl = tid + rep * 256;
        int row = fl >> 4, u4 = fl & 15;
        uint4 v = (r0 + row < M) ? *(const uint4*)&A[(size_t)(r0 + row) * H + u4 * 8]
                                 : make_uint4(0u, 0u, 0u, 0u);
        *(uint4*)&As[row][u4 * 8] = v;
    }
}

__device__ __forceinline__ void stage_W(const __half* __restrict__ Wt, __half (*Ws)[APAD], int tid) {
#pragma unroll
    for (int rep = 0; rep < 8; rep++) {
        int w = tid + rep * 256;
        int n = w >> 4, kg = w & 15;
        *(uint4*)&Ws[n][kg * 8] = *(const uint4*)&Wt[n * H + kg * 8];
    }
}

__device__ __forceinline__ void stage_W64(const __half* __restrict__ Wt, __half (*Ws)[APAD], int tid) {
#pragma unroll
    for (int rep = 0; rep < 4; rep++) {
        int w = tid + rep * 256;
        int n = w >> 4, kg = w & 15;
        *(uint4*)&Ws[n][kg * 8] = *(const uint4*)&Wt[n * H + kg * 8];
    }
}

__device__ __forceinline__ void hmma32(const __half (*As)[APAD], const __half (*Ws)[APAD],
                                       float (&acc)[4][4], int warp_m, int warp_n,
                                       int tm, int tk) {
#pragma unroll
    for (int kc = 0; kc < 8; kc++) {
        int k0 = kc * 16;
        int mrow = warp_m * 16 + tm;
        unsigned a0 = *(const unsigned*)&As[mrow][k0 + tk];
        unsigned a1 = *(const unsigned*)&As[mrow + 8][k0 + tk];
        unsigned a2 = *(const unsigned*)&As[mrow][k0 + 8 + tk];
        unsigned a3 = *(const unsigned*)&As[mrow + 8][k0 + 8 + tk];
#pragma unroll
        for (int nt = 0; nt < 4; nt++) {
            int n0 = warp_n * 32 + nt * 8;
            unsigned b0 = *(const unsigned*)&Ws[n0 + tm][k0 + tk];
            unsigned b1 = *(const unsigned*)&Ws[n0 + tm][k0 + 8 + tk];
            hmma16816(acc[nt][0], acc[nt][1], acc[nt][2], acc[nt][3], a0, a1, a2, a3, b0, b1);
        }
    }
}

__device__ __forceinline__ void zero4(float (&acc)[4][4]) {
#pragma unroll
    for (int nt = 0; nt < 4; nt++)
#pragma unroll
        for (int i = 0; i < 4; i++) acc[nt][i] = 0.f;
}

// xf(fp16) = h(fp32) @ W  (layer 0)
__global__ void __launch_bounds__(256) gemm_xf(const float* __restrict__ A,
                                               const __half* __restrict__ Wt,
                                               __half* __restrict__ out, int M) {
    __shared__ __half As[32][APAD];
    __shared__ __half Ws[128][APAD];
    int tid = threadIdx.x;
    int warp = tid >> 5, lane = tid & 31;
    int warp_m = warp >> 2, warp_n = warp & 3;
    int tm = lane >> 2, tk = (lane & 3) * 2;
    int r0 = blockIdx.x * 32;
    stage_A32(A, As, r0, M, tid);
    stage_W(Wt, Ws, tid);
    __syncthreads();
    float acc[4][4];
    zero4(acc);
    hmma32(As, Ws, acc, warp_m, warp_n, tm, tk);
    int row1 = r0 + warp_m * 16 + tm;
    int row2 = row1 + 8;
#pragma unroll
    for (int nt = 0; nt < 4; nt++) {
        int col = warp_n * 32 + nt * 8 + tk;
        if (row1 < M) *(__half2*)&out[(size_t)row1 * H + col] = __floats2half2_rn(acc[nt][0], acc[nt][1]);
        if (row2 < M) *(__half2*)&out[(size_t)row2 * H + col] = __floats2half2_rn(acc[nt][2], acc[nt][3]);
    }
}

// ======================= Edge gather (nearest-bin table) ======
__global__ void edge_gather(const __half* __restrict__ tab, int N) {
    int warp = (blockIdx.x * blockDim.x + threadIdx.x) >> 5;
    int lane = threadIdx.x & 31;
    if (warp >= N) return;
    int beg = g_rowptr[warp], end = g_rowptr[warp + 1];
    float a0 = 0.f, a1 = 0.f, a2 = 0.f, a3 = 0.f;
#pragma unroll 4
    for (int i = beg; i < end; i++) {
        int2 sd = g_csr[i];
        float d = __int_as_float(sd.y);
        float u = d * ((float)NBINS / CUTOFF_F) + 0.5f;
        int i0 = min(max((int)u, 0), NBINS);
        uint2 tp = *(const uint2*)&tab[(size_t)i0 * H + lane * 4];
        uint2 xq = *(const uint2*)&g_xfh[(size_t)sd.x * H + lane * 4];
        float2 w0 = __half22float2(*(__half2*)&tp.x);
        float2 w1 = __half22float2(*(__half2*)&tp.y);
        float2 xa = __half22float2(*(__half2*)&xq.x);
        float2 xb = __half22float2(*(__half2*)&xq.y);
        a0 += xa.x * w0.x;
        a1 += xa.y * w0.y;
        a2 += xb.x * w1.x;
        a3 += xb.y * w1.y;
    }
    __half2* op = (__half2*)&g_aggh[(size_t)warp * H + lane * 4];
    op[0] = __floats2half2_rn(a0, a1);
    op[1] = __floats2half2_rn(a2, a3);
}

// h += ssp(aggh @ W2 + b2) @ W3 + b3;  then xf_next = h_new @ W1n
__global__ void __launch_bounds__(256) gemm_dualX(const __half* __restrict__ A,
                                                  const __half* __restrict__ W2t,
                                                  const float* __restrict__ b2,
                                                  const __half* __restrict__ W3t,
                                                  const float* __restrict__ b3,
                                                  float* __restrict__ hio,
                                                  const __half* __restrict__ W1n,
                                                  __half* __restrict__ xfo, int M) {
    __shared__ __half As[32][APAD];
    __shared__ __half Ws[128][APAD];
    int tid = threadIdx.x;
    int warp = tid >> 5, lane = tid & 31;
    int warp_m = warp >> 2, warp_n = warp & 3;
    int tm = lane >> 2, tk = (lane & 3) * 2;
    int r0 = blockIdx.x * 32;
    int lr1 = warp_m * 16 + tm, lr2 = lr1 + 8;
    int row1 = r0 + lr1, row2 = r0 + lr2;

    stage_Ah32(A, As, r0, M, tid);
    stage_W(W2t, Ws, tid);
    __syncthreads();
    float acc[4][4];
    zero4(acc);
    hmma32(As, Ws, acc, warp_m, warp_n, tm, tk);
    __syncthreads();
#pragma unroll
    for (int nt = 0; nt < 4; nt++) {
        int col = warp_n * 32 + nt * 8 + tk;
        float2 bb = *(const float2*)&b2[col];
        *(__half2*)&As[lr1][col] = __floats2half2_rn(sspf(acc[nt][0] + bb.x), sspf(acc[nt][1] + bb.y));
        *(__half2*)&As[lr2][col] = __floats2half2_rn(sspf(acc[nt][2] + bb.x), sspf(acc[nt][3] + bb.y));
    }
    stage_W(W3t, Ws, tid);
    __syncthreads();
    zero4(acc);
    hmma32(As, Ws, acc, warp_m, warp_n, tm, tk);
    __syncthreads();
#pragma unroll
    for (int nt = 0; nt < 4; nt++) {
        int col = warp_n * 32 + nt * 8 + tk;
        float2 bb = *(const float2*)&b3[col];
        float2 o1 = make_float2(0.f, 0.f), o2 = make_float2(0.f, 0.f);
        if (row1 < M) o1 = *(const float2*)&hio[(size_t)row1 * H + col];
        if (row2 < M) o2 = *(const float2*)&hio[(size_t)row2 * H + col];
        o1.x += acc[nt][0] + bb.x; o1.y += acc[nt][1] + bb.y;
        o2.x += acc[nt][2] + bb.x; o2.y += acc[nt][3] + bb.y;
        if (row1 < M) *(float2*)&hio[(size_t)row1 * H + col] = o1;
        if (row2 < M) *(float2*)&hio[(size_t)row2 * H + col] = o2;
        *(__half2*)&As[lr1][col] = __floats2half2_rn(o1.x, o1.y);
        *(__half2*)&As[lr2][col] = __floats2half2_rn(o2.x, o2.y);
    }
    if (W1n) {
        stage_W(W1n, Ws, tid);
        __syncthreads();
        zero4(acc);
        hmma32(As, Ws, acc, warp_m, warp_n, tm, tk);
#pragma unroll
        for (int nt = 0; nt < 4; nt++) {
            int col = warp_n * 32 + nt * 8 + tk;
            if (row1 < M) *(__half2*)&xfo[(size_t)row1 * H + col] = __floats2half2_rn(acc[nt][0], acc[nt][1]);
            if (row2 < M) *(__half2*)&xfo[(size_t)row2 * H + col] = __floats2half2_rn(acc[nt][2], acc[nt][3]);
        }
    }
}

// ======================= Readout: colsum of ssp(h @ o1w + b1) via HMMA ====
__global__ void __launch_bounds__(256) readout_h(const float* __restrict__ A,
                                                 const float* __restrict__ b1, int M) {
    __shared__ __half As[64][APAD];
    __shared__ __half Ws[64][APAD];
    __shared__ float scol[64];
    int tid = threadIdx.x;
    int warp = tid >> 5, lane = tid & 31;
    int warp_m = warp >> 2, warp_n = warp & 3;
    int tm = lane >> 2, tk = (lane & 3) * 2;
    int r0 = blockIdx.x * 64;
    if (tid < 64) scol[tid] = 0.f;
#pragma unroll
    for (int rep = 0; rep < 8; rep++) {
        int fl = tid + rep * 256;
        int row = fl >> 5, f4 = fl & 31;
        float4 v = (r0 + row < M) ? *(const float4*)&A[(size_t)(r0 + row) * H + f4 * 4]
                                  : make_float4(0.f, 0.f, 0.f, 0.f);
        __half2* p = (__half2*)&As[row][f4 * 4];
        p[0] = __floats2half2_rn(v.x, v.y);
        p[1] = __floats2half2_rn(v.z, v.w);
    }
    stage_W64(g_o1t, Ws, tid);
    __syncthreads();
    float acc[2][2][4];
#pragma unroll
    for (int m = 0; m < 2; m++)
#pragma unroll
        for (int nt = 0; nt < 2; nt++)
#pragma unroll
            for (int i = 0; i < 4; i++) acc[m][nt][i] = 0.f;
#pragma unroll
    for (int msub = 0; msub < 2; msub++) {
        int mrow = msub * 32 + warp_m * 16 + tm;
#pragma unroll
        for (int kc = 0; kc < 8; kc++) {
            int k0 = kc * 16;
            unsigned a0 = *(const unsigned*)&As[mrow][k0 + tk];
            unsigned a1 = *(const unsigned*)&As[mrow + 8][k0 + tk];
            unsigned a2 = *(const unsigned*)&As[mrow][k0 + 8 + tk];
            unsigned a3 = *(const unsigned*)&As[mrow + 8][k0 + 8 + tk];
#pragma unroll
            for (int nt = 0; nt < 2; nt++) {
                int n0 = warp_n * 16 + nt * 8;
                unsigned b0 = *(const unsigned*)&Ws[n0 + tm][k0 + tk];
                unsigned bq1 = *(const unsigned*)&Ws[n0 + tm][k0 + 8 + tk];
                hmma16816(acc[msub][nt][0], acc[msub][nt][1], acc[msub][nt][2], acc[msub][nt][3],
                          a0, a1, a2, a3, b0, bq1);
            }
        }
    }
    float cs[2][2] = {{0.f, 0.f}, {0.f, 0.f}};
#pragma unroll
    for (int msub = 0; msub < 2; msub++) {
        int row1 = r0 + msub * 32 + warp_m * 16 + tm;
        int row2 = row1 + 8;
#pragma unroll
        for (int nt = 0; nt < 2; nt++) {
            int col = warp_n * 16 + nt * 8 + tk;
            float2 bb = *(const float2*)&b1[col];
            if (row1 < M) {
                cs[nt][0] += sspf(acc[msub][nt][0] + bb.x);
                cs[nt][1] += sspf(acc[msub][nt][1] + bb.y);
            }
            if (row2 < M) {
                cs[nt][0] += sspf(acc[msub][nt][2] + bb.x);
                cs[nt][1] += sspf(acc[msub][nt][3] + bb.y);
            }
        }
    }
#pragma unroll
    for (int off = 16; off >= 4; off >>= 1) {
#pragma unroll
        for (int nt = 0; nt < 2; nt++) {
            cs[nt][0] += __shfl_down_sync(0xffffffffu, cs[nt][0], off);
            cs[nt][1] += __shfl_down_sync(0xffffffffu, cs[nt][1], off);
        }
    }
    if (lane < 4) {
#pragma unroll
        for (int nt = 0; nt < 2; nt++) {
            int col = warp_n * 16 + nt * 8 + lane * 2;
            atomicAdd(&scol[col], cs[nt][0]);
            atomicAdd(&scol[col + 1], cs[nt][1]);
        }
    }
    __syncthreads();
    if (tid < 64) atomicAdd(&g_acc[tid], scol[tid]);
}

__global__ void readout_final(const float* __restrict__ o2w, const float* __restrict__ o2b,
                              const float* __restrict__ rw, const float* __restrict__ rb,
                              float* __restrict__ out, int N) {
    __shared__ float v[64];
    int t = threadIdx.x;
    float a = (float)N * o2b[t];
#pragma unroll 8
    for (int j = 0; j < 64; j++) a += g_acc[j] * o2w[j * 64 + t];
    v[t] = a;
    __syncthreads();
    if (t < 12) {
        float r = rb[t];
#pragma unroll
        for (int j = 0; j < 64; j++) r += v[j] * rw[j * 12 + t];
        out[t] = r;
    }
}

extern "C" void kernel_launch(void* const* d_in, const int* in_sizes, int n_in,
                              void* d_out, int out_size) {
    const int*   x    = (const int*)d_in[0];
    const int*   ei   = (const int*)d_in[1];
    const float* dist = (const float*)d_in[2];
    const float* emb  = (const float*)d_in[3];
    const float* mw1  = (const float*)d_in[4];
    const float* mb1  = (const float*)d_in[5];
    const float* mw2  = (const float*)d_in[6];
    const float* mb2  = (const float*)d_in[7];
    const float* l1w  = (const float*)d_in[8];
    const float* l2w  = (const float*)d_in[9];
    const float* l2b  = (const float*)d_in[10];
    const float* lw   = (const float*)d_in[11];
    const float* lb   = (const float*)d_in[12];
    const float* o1w  = (const float*)d_in[13];
    const float* o1b  = (const float*)d_in[14];
    const float* o2w  = (const float*)d_in[15];
    const float* o2b  = (const float*)d_in[16];
    const float* rw   = (const float*)d_in[17];
    const float* rb   = (const float*)d_in[18];

    int N = in_sizes[0];
    int E = in_sizes[2];
    int L = in_sizes[4] / (G * H);

    float *pacc;
    int *prow;
    cudaGetSymbolAddress((void**)&pacc, g_acc);
    cudaGetSymbolAddress((void**)&prow, g_rowptr);
    float *ph;
    __half *pxfh, *paggh, *pw1t, *pw2t, *pw3t, *ptab;
    cudaGetSymbolAddress((void**)&ph, g_h);
    cudaGetSymbolAddress((void**)&pxfh, g_xfh);
    cudaGetSymbolAddress((void**)&paggh, g_aggh);
    cudaGetSymbolAddress((void**)&pw1t, g_w1t);
    cudaGetSymbolAddress((void**)&pw2t, g_w2t);
    cudaGetSymbolAddress((void**)&pw3t, g_w3t);
    cudaGetSymbolAddress((void**)&ptab, g_tab);

    const int* esrc = ei;
    const int* edst = ei + E;

    int nb32 = (N + 31) / 32;
    int nb64 = (N + 63) / 64;
    int nbE = (N + 7) / 8;

    embed_kernel<<<N, 128>>>(x, emb, N);
    cudaMemsetAsync(prow, 0, (N + 1) * sizeof(int));
    hist_kernel<<<(E + 255) / 256, 256>>>(edst, E);
    scan_kernel<<<1, 1024>>>(N + 1);
    scatter_kernel<<<(E + 255) / 256, 256>>>(esrc, edst, dist, E);
    convert_weights<<<256, 256>>>(l1w, l2w, lw, o1w, L);
    gemm_xf<<<nb32, 256>>>(ph, pw1t, pxfh, N);
    dim3 tgrid((NBINS + 1 + BPB - 1) / BPB, L);
    table_all<<<tgrid, 128>>>(mw1, mb1, mw2, mb2);

    for (int l = 0; l < L; l++) {
        edge_gather<<<nbE, 256>>>(ptab + (size_t)l * (NBINS + 1) * H, N);
        const __half* w1n = (l + 1 < L) ? pw1t + (size_t)(l + 1) * H * H : nullptr;
        gemm_dualX<<<nb32, 256>>>(paggh, pw2t + (size_t)l * H * H, l2b + (size_t)l * H,
                                  pw3t + (size_t)l * H * H, lb + (size_t)l * H,
                                  ph, w1n, pxfh, N);
    }

    cudaMemsetAsync(pacc, 0, 64 * sizeof(float));
    readout_h<<<nb64, 256>>>(ph, o1b, N);
    readout_final<<<1, 64>>>(o2w, o2b, rw, rb, (float*)d_out, N);
}

// round 15
// speedup vs baseline: 1.2589x; 1.0269x over previous
#include <cuda_runtime.h>
#include <cuda_fp16.h>
#include <math.h>

#define H 128
#define G 50
#define NBINS 2048
#define BPB 16
#define CUTOFF_F 10.0f
#define NMAX 10000
#define EMAX 320000
#define LMAX 6
#define PI_F 3.14159265358979323846f

__device__ __align__(16) float  g_h[NMAX * H];
__device__ __align__(16) __half g_xfh[NMAX * H];
__device__ __align__(16) __half g_aggh[NMAX * H];
__device__ __align__(16) __half g_tab[LMAX * (NBINS + 1) * H];
__device__ float g_acc[64];
__device__ int  g_rowptr[NMAX + 1];
__device__ int  g_rank[EMAX];
__device__ __align__(16) int2 g_csr[EMAX];
__device__ __align__(16) __half g_w1t[LMAX * H * H];
__device__ __align__(16) __half g_w2t[LMAX * H * H];
__device__ __align__(16) __half g_w3t[LMAX * H * H];
__device__ __align__(16) __half g_o1t[64 * H];

__device__ __forceinline__ float sspf(float x) {
    return fmaxf(x, 0.f) + log1pf(expf(-fabsf(x))) - 0.69314718055994530942f;
}

// ---- f32x2 helpers (table build) ----
__device__ __forceinline__ void fma2(unsigned long long& d, unsigned long long a, unsigned long long b) {
    asm("fma.rn.f32x2 %0, %1, %2, %0;" : "+l"(d) : "l"(a), "l"(b));
}
__device__ __forceinline__ unsigned long long bcast2(float a) {
    unsigned long long r; asm("mov.b64 %0, {%1, %1};" : "=l"(r) : "f"(a)); return r;
}
__device__ __forceinline__ unsigned long long pack2(float a, float b) {
    unsigned long long r; asm("mov.b64 %0, {%1, %2};" : "=l"(r) : "f"(a), "f"(b)); return r;
}
__device__ __forceinline__ float2 unpack2(unsigned long long v) {
    float2 f; asm("mov.b64 {%0, %1}, %2;" : "=f"(f.x), "=f"(f.y) : "l"(v)); return f;
}

// ---- HMMA m16n8k16 ----
__device__ __forceinline__ void hmma16816(float& c0, float& c1, float& c2, float& c3,
                                          unsigned a0, unsigned a1, unsigned a2, unsigned a3,
                                          unsigned b0, unsigned b1) {
    asm volatile(
        "mma.sync.aligned.m16n8k16.row.col.f32.f16.f16.f32 "
        "{%0,%1,%2,%3}, {%4,%5,%6,%7}, {%8,%9}, {%0,%1,%2,%3};"
        : "+f"(c0), "+f"(c1), "+f"(c2), "+f"(c3)
        : "r"(a0), "r"(a1), "r"(a2), "r"(a3), "r"(b0), "r"(b1));
}

__global__ void convert_weights(const float* __restrict__ w1, const float* __restrict__ w2,
                                const float* __restrict__ w3, const float* __restrict__ o1w, int L) {
    int total = L * H * H;
    for (int idx = blockIdx.x * blockDim.x + threadIdx.x; idx < total; idx += gridDim.x * blockDim.x) {
        int l = idx >> 14;
        int r = idx & 16383;
        int k = r >> 7, n = r & 127;
        int o = (l << 14) + (n << 7) + k;
        g_w1t[o] = __float2half(w1[idx]);
        g_w2t[o] = __float2half(w2[idx]);
        g_w3t[o] = __float2half(w3[idx]);
    }
    for (int idx = blockIdx.x * blockDim.x + threadIdx.x; idx < H * 64; idx += gridDim.x * blockDim.x) {
        int k = idx >> 6, n = idx & 63;
        g_o1t[n * H + k] = __float2half(o1w[idx]);
    }
}

// ======================= CSR build =======================
__global__ void hist_kernel(const int* __restrict__ dst, int E) {
    int e = blockIdx.x * blockDim.x + threadIdx.x;
    if (e < E) g_rank[e] = atomicAdd(&g_rowptr[dst[e] + 1], 1);
}

__global__ void __launch_bounds__(1024) scan_kernel(int n) {
    __shared__ int buf[10240];
    __shared__ int wsum[32];
    int t = threadIdx.x;
    const int C = 10;
    for (int i = t; i < 10240; i += 1024) buf[i] = (i < n) ? g_rowptr[i] : 0;
    __syncthreads();
    int base = t * C;
    int s = 0;
#pragma unroll
    for (int i = 0; i < C; i++) s += buf[base + i];
    int lane = t & 31, w = t >> 5;
    int v = s;
#pragma unroll
    for (int off = 1; off < 32; off <<= 1) {
        int u = __shfl_up_sync(0xffffffffu, v, off);
        if (lane >= off) v += u;
    }
    if (lane == 31) wsum[w] = v;
    __syncthreads();
    if (w == 0) {
        int xv = wsum[lane];
#pragma unroll
        for (int off = 1; off < 32; off <<= 1) {
            int u = __shfl_up_sync(0xffffffffu, xv, off);
            if (lane >= off) xv += u;
        }
        wsum[lane] = xv;
    }
    __syncthreads();
    int run = v - s + (w > 0 ? wsum[w - 1] : 0);
#pragma unroll
    for (int i = 0; i < C; i++) { run += buf[base + i]; buf[base + i] = run; }
    __syncthreads();
    for (int i = t; i < n; i += 1024) g_rowptr[i] = buf[i];
}

__global__ void scatter_kernel(const int* __restrict__ src, const int* __restrict__ dst,
                               const float* __restrict__ dist, int E) {
    int e = blockIdx.x * blockDim.x + threadIdx.x;
    if (e < E) {
        int p = g_rowptr[dst[e]] + g_rank[e];
        g_csr[p] = make_int2(src[e], __float_as_int(dist[e]));
    }
}

// ======================= Filter tables: 16 bins/block, paired fma2 ====
__global__ void __launch_bounds__(128) table_all(
    const float* __restrict__ mw1, const float* __restrict__ mb1,
    const float* __restrict__ mw2, const float* __restrict__ mb2)
{
    __shared__ unsigned long long eas2[BPB / 2][G];
    __shared__ unsigned long long a_s2[BPB / 2][H];
    int f = threadIdx.x;
    int b0 = blockIdx.x * BPB;
    int l = blockIdx.y;
    const float* w1 = mw1 + (size_t)l * G * H;
    const float* b1 = mb1 + (size_t)l * H;
    const float* w2 = mw2 + (size_t)l * H * H;
    const float* b2 = mb2 + (size_t)l * H;
    __half* tab = g_tab + (size_t)l * (NBINS + 1) * H;
    const float spacing = CUTOFF_F / (G - 1);
    const float coeff = -0.5f / (spacing * spacing);
    const float binw = CUTOFF_F / NBINS;

    for (int i = f; i < (BPB / 2) * G; i += 128) {
        int p = i / G, g = i - p * G;
        float dA = (b0 + 2 * p) * binw;
        float dB = dA + binw;
        float xA = dA - g * spacing, xB = dB - g * spacing;
        eas2[p][g] = pack2(expf(coeff * xA * xA), expf(coeff * xB * xB));
    }
    __syncthreads();

    unsigned long long a2[BPB / 2];
    {
        unsigned long long bvv = bcast2(b1[f]);
#pragma unroll
        for (int p = 0; p < BPB / 2; p++) a2[p] = bvv;
    }
#pragma unroll 2
    for (int g = 0; g < G; g++) {
        unsigned long long wb = bcast2(w1[g * H + f]);
#pragma unroll
        for (int p = 0; p < BPB / 2; p++) fma2(a2[p], eas2[p][g], wb);
    }
#pragma unroll
    for (int p = 0; p < BPB / 2; p++) {
        float2 v = unpack2(a2[p]);
        a_s2[p][f] = pack2(sspf(v.x), sspf(v.y));
    }
    __syncthreads();

    unsigned long long acc[BPB / 2];
#pragma unroll
    for (int p = 0; p < BPB / 2; p++) acc[p] = 0ull;
#pragma unroll 4
    for (int j = 0; j < H; j++) {
        unsigned long long wb = bcast2(w2[j * H + f]);
#pragma unroll
        for (int p = 0; p < BPB / 2; p++) fma2(acc[p], a_s2[p][j], wb);
    }
    float b2v = b2[f];
#pragma unroll
    for (int p = 0; p < BPB / 2; p++) {
        float2 v = unpack2(acc[p]);
        int bA = b0 + 2 * p, bB = bA + 1;
        float cA = 0.5f * (cosf(bA * binw * (PI_F / CUTOFF_F)) + 1.f);
        float cB = 0.5f * (cosf(bB * binw * (PI_F / CUTOFF_F)) + 1.f);
        if (bA <= NBINS) tab[(size_t)bA * H + f] = __float2half((v.x + b2v) * cA);
        if (bB <= NBINS) tab[(size_t)bB * H + f] = __float2half((v.y + b2v) * cB);
    }
}

// ======================= HMMA common (32-row tiles) =======================
#define APAD 136

__device__ __forceinline__ void stage_Ah32(const __half* __restrict__ A, __half (*As)[APAD],
                                           int r0, int M, int tid) {
#pragma unroll
    for (int rep = 0; rep < 2; rep++) {
        int fl = tid + rep * 256;
        int row = fl >> 4, u4 = fl & 15;
        uint4 v = (r0 + row < M) ? *(const uint4*)&A[(size_t)(r0 + row) * H + u4 * 8]
                                 : make_uint4(0u, 0u, 0u, 0u);
        *(uint4*)&As[row][u4 * 8] = v;
    }
}

__device__ __forceinline__ void stage_W(const __half* __restrict__ Wt, __half (*Ws)[APAD], int tid) {
#pragma unroll
    for (int rep = 0; rep < 8; rep++) {
        int w = tid + rep * 256;
        int n = w >> 4, kg = w & 15;
        *(uint4*)&Ws[n][kg * 8] = *(const uint4*)&Wt[n * H + kg * 8];
    }
}

// register prefetch: LDG now, STS later
__device__ __forceinline__ void ldg_W(const __half* __restrict__ Wt, uint4 (&r)[8], int tid) {
#pragma unroll
    for (int rep = 0; rep < 8; rep++) {
        int w = tid + rep * 256;
        int n = w >> 4, kg = w & 15;
        r[rep] = *(const uint4*)&Wt[n * H + kg * 8];
    }
}
__device__ __forceinline__ void sts_W(const uint4 (&r)[8], __half (*Ws)[APAD], int tid) {
#pragma unroll
    for (int rep = 0; rep < 8; rep++) {
        int w = tid + rep * 256;
        int n = w >> 4, kg = w & 15;
        *(uint4*)&Ws[n][kg * 8] = r[rep];
    }
}

__device__ __forceinline__ void stage_W64(const __half* __restrict__ Wt, __half (*Ws)[APAD], int tid) {
#pragma unroll
    for (int rep = 0; rep < 4; rep++) {
        int w = tid + rep * 256;
        int n = w >> 4, kg = w & 15;
        *(uint4*)&Ws[n][kg * 8] = *(const uint4*)&Wt[n * H + kg * 8];
    }
}

__device__ __forceinline__ void hmma32(const __half (*As)[APAD], const __half (*Ws)[APAD],
                                       float (&acc)[4][4], int warp_m, int warp_n,
                                       int tm, int tk) {
#pragma unroll
    for (int kc = 0; kc < 8; kc++) {
        int k0 = kc * 16;
        int mrow = warp_m * 16 + tm;
        unsigned a0 = *(const unsigned*)&As[mrow][k0 + tk];
        unsigned a1 = *(const unsigned*)&As[mrow + 8][k0 + tk];
        unsigned a2 = *(const unsigned*)&As[mrow][k0 + 8 + tk];
        unsigned a3 = *(const unsigned*)&As[mrow + 8][k0 + 8 + tk];
#pragma unroll
        for (int nt = 0; nt < 4; nt++) {
            int n0 = warp_n * 32 + nt * 8;
            unsigned b0 = *(const unsigned*)&Ws[n0 + tm][k0 + tk];
            unsigned b1 = *(const unsigned*)&Ws[n0 + tm][k0 + 8 + tk];
            hmma16816(acc[nt][0], acc[nt][1], acc[nt][2], acc[nt][3], a0, a1, a2, a3, b0, b1);
        }
    }
}

__device__ __forceinline__ void zero4(float (&acc)[4][4]) {
#pragma unroll
    for (int nt = 0; nt < 4; nt++)
#pragma unroll
        for (int i = 0; i < 4; i++) acc[nt][i] = 0.f;
}

// layer 0: h = emb[x]; xf = h @ W1   (embed fused into staging)
__global__ void __launch_bounds__(256) gemm_xf0(const int* __restrict__ x,
                                                const float* __restrict__ emb,
                                                const __half* __restrict__ Wt,
                                                float* __restrict__ hout,
                                                __half* __restrict__ xfo, int M) {
    __shared__ __half As[32][APAD];
    __shared__ __half Ws[128][APAD];
    int tid = threadIdx.x;
    int warp = tid >> 5, lane = tid & 31;
    int warp_m = warp >> 2, warp_n = warp & 3;
    int tm = lane >> 2, tk = (lane & 3) * 2;
    int r0 = blockIdx.x * 32;
#pragma unroll
    for (int rep = 0; rep < 4; rep++) {
        int fl = tid + rep * 256;
        int row = fl >> 5, f4 = fl & 31;
        float4 v = make_float4(0.f, 0.f, 0.f, 0.f);
        if (r0 + row < M) {
            v = *(const float4*)&emb[(size_t)x[r0 + row] * H + f4 * 4];
            *(float4*)&hout[(size_t)(r0 + row) * H + f4 * 4] = v;
        }
        __half2* p = (__half2*)&As[row][f4 * 4];
        p[0] = __floats2half2_rn(v.x, v.y);
        p[1] = __floats2half2_rn(v.z, v.w);
    }
    stage_W(Wt, Ws, tid);
    __syncthreads();
    float acc[4][4];
    zero4(acc);
    hmma32(As, Ws, acc, warp_m, warp_n, tm, tk);
    int row1 = r0 + warp_m * 16 + tm;
    int row2 = row1 + 8;
#pragma unroll
    for (int nt = 0; nt < 4; nt++) {
        int col = warp_n * 32 + nt * 8 + tk;
        if (row1 < M) *(__half2*)&xfo[(size_t)row1 * H + col] = __floats2half2_rn(acc[nt][0], acc[nt][1]);
        if (row2 < M) *(__half2*)&xfo[(size_t)row2 * H + col] = __floats2half2_rn(acc[nt][2], acc[nt][3]);
    }
}

// ======================= Edge gather (nearest-bin table) ======
__global__ void edge_gather(const __half* __restrict__ tab, int N) {
    int warp = (blockIdx.x * blockDim.x + threadIdx.x) >> 5;
    int lane = threadIdx.x & 31;
    if (warp >= N) return;
    int beg = g_rowptr[warp], end = g_rowptr[warp + 1];
    float a0 = 0.f, a1 = 0.f, a2 = 0.f, a3 = 0.f;
#pragma unroll 4
    for (int i = beg; i < end; i++) {
        int2 sd = g_csr[i];
        float d = __int_as_float(sd.y);
        float u = d * ((float)NBINS / CUTOFF_F) + 0.5f;
        int i0 = min(max((int)u, 0), NBINS);
        uint2 tp = *(const uint2*)&tab[(size_t)i0 * H + lane * 4];
        uint2 xq = *(const uint2*)&g_xfh[(size_t)sd.x * H + lane * 4];
        float2 w0 = __half22float2(*(__half2*)&tp.x);
        float2 w1 = __half22float2(*(__half2*)&tp.y);
        float2 xa = __half22float2(*(__half2*)&xq.x);
        float2 xb = __half22float2(*(__half2*)&xq.y);
        a0 += xa.x * w0.x;
        a1 += xa.y * w0.y;
        a2 += xb.x * w1.x;
        a3 += xb.y * w1.y;
    }
    __half2* op = (__half2*)&g_aggh[(size_t)warp * H + lane * 4];
    op[0] = __floats2half2_rn(a0, a1);
    op[1] = __floats2half2_rn(a2, a3);
}

// h += ssp(aggh @ W2 + b2) @ W3 + b3;  then xf_next = h_new @ W1n
// W3 / W1n are register-prefetched during the previous HMMA stage.
__global__ void __launch_bounds__(256) gemm_dualX(const __half* __restrict__ A,
                                                  const __half* __restrict__ W2t,
                                                  const float* __restrict__ b2,
                                                  const __half* __restrict__ W3t,
                                                  const float* __restrict__ b3,
                                                  float* __restrict__ hio,
                                                  const __half* __restrict__ W1n,
                                                  __half* __restrict__ xfo, int M) {
    __shared__ __half As[32][APAD];
    __shared__ __half Ws[128][APAD];
    int tid = threadIdx.x;
    int warp = tid >> 5, lane = tid & 31;
    int warp_m = warp >> 2, warp_n = warp & 3;
    int tm = lane >> 2, tk = (lane & 3) * 2;
    int r0 = blockIdx.x * 32;
    int lr1 = warp_m * 16 + tm, lr2 = lr1 + 8;
    int row1 = r0 + lr1, row2 = r0 + lr2;

    stage_Ah32(A, As, r0, M, tid);
    stage_W(W2t, Ws, tid);
    uint4 wreg[8];
    ldg_W(W3t, wreg, tid);            // prefetch W3 during stage-1 HMMA
    __syncthreads();
    float acc[4][4];
    zero4(acc);
    hmma32(As, Ws, acc, warp_m, warp_n, tm, tk);
    __syncthreads();
#pragma unroll
    for (int nt = 0; nt < 4; nt++) {
        int col = warp_n * 32 + nt * 8 + tk;
        float2 bb = *(const float2*)&b2[col];
        *(__half2*)&As[lr1][col] = __floats2half2_rn(sspf(acc[nt][0] + bb.x), sspf(acc[nt][1] + bb.y));
        *(__half2*)&As[lr2][col] = __floats2half2_rn(sspf(acc[nt][2] + bb.x), sspf(acc[nt][3] + bb.y));
    }
    sts_W(wreg, Ws, tid);             // W3 -> smem (LDG latency already absorbed)
    if (W1n) ldg_W(W1n, wreg, tid);   // prefetch W1n during stage-2 HMMA
    __syncthreads();
    zero4(acc);
    hmma32(As, Ws, acc, warp_m, warp_n, tm, tk);
    __syncthreads();
#pragma unroll
    for (int nt = 0; nt < 4; nt++) {
        int col = warp_n * 32 + nt * 8 + tk;
        float2 bb = *(const float2*)&b3[col];
        float2 o1 = make_float2(0.f, 0.f), o2 = make_float2(0.f, 0.f);
        if (row1 < M) o1 = *(const float2*)&hio[(size_t)row1 * H + col];
        if (row2 < M) o2 = *(const float2*)&hio[(size_t)row2 * H + col];
        o1.x += acc[nt][0] + bb.x; o1.y += acc[nt][1] + bb.y;
        o2.x += acc[nt][2] + bb.x; o2.y += acc[nt][3] + bb.y;
        if (row1 < M) *(float2*)&hio[(size_t)row1 * H + col] = o1;
        if (row2 < M) *(float2*)&hio[(size_t)row2 * H + col] = o2;
        *(__half2*)&As[lr1][col] = __floats2half2_rn(o1.x, o1.y);
        *(__half2*)&As[lr2][col] = __floats2half2_rn(o2.x, o2.y);
    }
    if (W1n) {
        sts_W(wreg, Ws, tid);
        __syncthreads();
        zero4(acc);
        hmma32(As, Ws, acc, warp_m, warp_n, tm, tk);
#pragma unroll
        for (int nt = 0; nt < 4; nt++) {
            int col = warp_n * 32 + nt * 8 + tk;
            if (row1 < M) *(__half2*)&xfo[(size_t)row1 * H + col] = __floats2half2_rn(acc[nt][0], acc[nt][1]);
            if (row2 < M) *(__half2*)&xfo[(size_t)row2 * H + col] = __floats2half2_rn(acc[nt][2], acc[nt][3]);
        }
    }
}

// ======================= Readout: colsum of ssp(h @ o1w + b1) via HMMA ====
__global__ void __launch_bounds__(256) readout_h(const float* __restrict__ A,
                                                 const float* __restrict__ b1, int M) {
    __shared__ __half As[64][APAD];
    __shared__ __half Ws[64][APAD];
    __shared__ float scol[64];
    int tid = threadIdx.x;
    int warp = tid >> 5, lane = tid & 31;
    int warp_m = warp >> 2, warp_n = warp & 3;
    int tm = lane >> 2, tk = (lane & 3) * 2;
    int r0 = blockIdx.x * 64;
    if (tid < 64) scol[tid] = 0.f;
#pragma unroll
    for (int rep = 0; rep < 8; rep++) {
        int fl = tid + rep * 256;
        int row = fl >> 5, f4 = fl & 31;
        float4 v = (r0 + row < M) ? *(const float4*)&A[(size_t)(r0 + row) * H + f4 * 4]
                                  : make_float4(0.f, 0.f, 0.f, 0.f);
        __half2* p = (__half2*)&As[row][f4 * 4];
        p[0] = __floats2half2_rn(v.x, v.y);
        p[1] = __floats2half2_rn(v.z, v.w);
    }
    stage_W64(g_o1t, Ws, tid);
    __syncthreads();
    float acc[2][2][4];
#pragma unroll
    for (int m = 0; m < 2; m++)
#pragma unroll
        for (int nt = 0; nt < 2; nt++)
#pragma unroll
            for (int i = 0; i < 4; i++) acc[m][nt][i] = 0.f;
#pragma unroll
    for (int msub = 0; msub < 2; msub++) {
        int mrow = msub * 32 + warp_m * 16 + tm;
#pragma unroll
        for (int kc = 0; kc < 8; kc++) {
            int k0 = kc * 16;
            unsigned a0 = *(const unsigned*)&As[mrow][k0 + tk];
            unsigned a1 = *(const unsigned*)&As[mrow + 8][k0 + tk];
            unsigned a2 = *(const unsigned*)&As[mrow][k0 + 8 + tk];
            unsigned a3 = *(const unsigned*)&As[mrow + 8][k0 + 8 + tk];
#pragma unroll
            for (int nt = 0; nt < 2; nt++) {
                int n0 = warp_n * 16 + nt * 8;
                unsigned b0 = *(const unsigned*)&Ws[n0 + tm][k0 + tk];
                unsigned bq1 = *(const unsigned*)&Ws[n0 + tm][k0 + 8 + tk];
                hmma16816(acc[msub][nt][0], acc[msub][nt][1], acc[msub][nt][2], acc[msub][nt][3],
                          a0, a1, a2, a3, b0, bq1);
            }
        }
    }
    float cs[2][2] = {{0.f, 0.f}, {0.f, 0.f}};
#pragma unroll
    for (int msub = 0; msub < 2; msub++) {
        int row1 = r0 + msub * 32 + warp_m * 16 + tm;
        int row2 = row1 + 8;
#pragma unroll
        for (int nt = 0; nt < 2; nt++) {
            int col = warp_n * 16 + nt * 8 + tk;
            float2 bb = *(const float2*)&b1[col];
            if (row1 < M) {
                cs[nt][0] += sspf(acc[msub][nt][0] + bb.x);
                cs[nt][1] += sspf(acc[msub][nt][1] + bb.y);
            }
            if (row2 < M) {
                cs[nt][0] += sspf(acc[msub][nt][2] + bb.x);
                cs[nt][1] += sspf(acc[msub][nt][3] + bb.y);
            }
        }
    }
#pragma unroll
    for (int off = 16; off >= 4; off >>= 1) {
#pragma unroll
        for (int nt = 0; nt < 2; nt++) {
            cs[nt][0] += __shfl_down_sync(0xffffffffu, cs[nt][0], off);
            cs[nt][1] += __shfl_down_sync(0xffffffffu, cs[nt][1], off);
        }
    }
    if (lane < 4) {
#pragma unroll
        for (int nt = 0; nt < 2; nt++) {
            int col = warp_n * 16 + nt * 8 + lane * 2;
            atomicAdd(&scol[col], cs[nt][0]);
            atomicAdd(&scol[col + 1], cs[nt][1]);
        }
    }
    __syncthreads();
    if (tid < 64) atomicAdd(&g_acc[tid], scol[tid]);
}

__global__ void readout_final(const float* __restrict__ o2w, const float* __restrict__ o2b,
                              const float* __restrict__ rw, const float* __restrict__ rb,
                              float* __restrict__ out, int N) {
    __shared__ float v[64];
    int t = threadIdx.x;
    float a = (float)N * o2b[t];
#pragma unroll 8
    for (int j = 0; j < 64; j++) a += g_acc[j] * o2w[j * 64 + t];
    v[t] = a;
    __syncthreads();
    if (t < 12) {
        float r = rb[t];
#pragma unroll
        for (int j = 0; j < 64; j++) r += v[j] * rw[j * 12 + t];
        out[t] = r;
    }
}

extern "C" void kernel_launch(void* const* d_in, const int* in_sizes, int n_in,
                              void* d_out, int out_size) {
    const int*   x    = (const int*)d_in[0];
    const int*   ei   = (const int*)d_in[1];
    const float* dist = (const float*)d_in[2];
    const float* emb  = (const float*)d_in[3];
    const float* mw1  = (const float*)d_in[4];
    const float* mb1  = (const float*)d_in[5];
    const float* mw2  = (const float*)d_in[6];
    const float* mb2  = (const float*)d_in[7];
    const float* l1w  = (const float*)d_in[8];
    const float* l2w  = (const float*)d_in[9];
    const float* l2b  = (const float*)d_in[10];
    const float* lw   = (const float*)d_in[11];
    const float* lb   = (const float*)d_in[12];
    const float* o1w  = (const float*)d_in[13];
    const float* o1b  = (const float*)d_in[14];
    const float* o2w  = (const float*)d_in[15];
    const float* o2b  = (const float*)d_in[16];
    const float* rw   = (const float*)d_in[17];
    const float* rb   = (const float*)d_in[18];

    int N = in_sizes[0];
    int E = in_sizes[2];
    int L = in_sizes[4] / (G * H);

    float *pacc;
    int *prow;
    cudaGetSymbolAddress((void**)&pacc, g_acc);
    cudaGetSymbolAddress((void**)&prow, g_rowptr);
    float *ph;
    __half *pxfh, *paggh, *pw1t, *pw2t, *pw3t, *ptab;
    cudaGetSymbolAddress((void**)&ph, g_h);
    cudaGetSymbolAddress((void**)&pxfh, g_xfh);
    cudaGetSymbolAddress((void**)&paggh, g_aggh);
    cudaGetSymbolAddress((void**)&pw1t, g_w1t);
    cudaGetSymbolAddress((void**)&pw2t, g_w2t);
    cudaGetSymbolAddress((void**)&pw3t, g_w3t);
    cudaGetSymbolAddress((void**)&ptab, g_tab);

    const int* esrc = ei;
    const int* edst = ei + E;

    int nb32 = (N + 31) / 32;
    int nb64 = (N + 63) / 64;
    int nbE = (N + 7) / 8;

    cudaMemsetAsync(prow, 0, (N + 1) * sizeof(int));
    hist_kernel<<<(E + 255) / 256, 256>>>(edst, E);
    scan_kernel<<<1, 1024>>>(N + 1);
    scatter_kernel<<<(E + 255) / 256, 256>>>(esrc, edst, dist, E);
    convert_weights<<<256, 256>>>(l1w, l2w, lw, o1w, L);
    gemm_xf0<<<nb32, 256>>>(x, emb, pw1t, ph, pxfh, N);
    dim3 tgrid((NBINS + 1 + BPB - 1) / BPB, L);
    table_all<<<tgrid, 128>>>(mw1, mb1, mw2, mb2);

    for (int l = 0; l < L; l++) {
        edge_gather<<<nbE, 256>>>(ptab + (size_t)l * (NBINS + 1) * H, N);
        const __half* w1n = (l + 1 < L) ? pw1t + (size_t)(l + 1) * H * H : nullptr;
        gemm_dualX<<<nb32, 256>>>(paggh, pw2t + (size_t)l * H * H, l2b + (size_t)l * H,
                                  pw3t + (size_t)l * H * H, lb + (size_t)l * H,
                                  ph, w1n, pxfh, N);
    }

    cudaMemsetAsync(pacc, 0, 64 * sizeof(float));
    readout_h<<<nb64, 256>>>(ph, o1b, N);
    readout_final<<<1, 64>>>(o2w, o2b, rw, rb, (float*)d_out, N);
}

// round 16
// speedup vs baseline: 1.2960x; 1.0294x over previous
#include <cuda_runtime.h>
#include <cuda_fp16.h>
#include <math.h>

#define H 128
#define G 50
#define NBINS 2048
#define BPB 16
#define CUTOFF_F 10.0f
#define NMAX 10000
#define EMAX 320000
#define LMAX 6
#define PI_F 3.14159265358979323846f

__device__ __align__(16) float  g_h[NMAX * H];
__device__ __align__(16) __half g_xfh[NMAX * H];
__device__ __align__(16) __half g_aggh[NMAX * H];
__device__ __align__(16) __half g_tab[LMAX * (NBINS + 1) * H];
__device__ float g_acc[64];
__device__ int  g_rowptr[NMAX + 1];
__device__ int  g_rank[EMAX];
__device__ __align__(16) int2 g_csr[EMAX];
__device__ __align__(16) __half g_w1t[LMAX * H * H];
__device__ __align__(16) __half g_w2t[LMAX * H * H];
__device__ __align__(16) __half g_w3t[LMAX * H * H];
__device__ __align__(16) __half g_o1t[64 * H];

__device__ __forceinline__ float sspf(float x) {
    return fmaxf(x, 0.f) + log1pf(expf(-fabsf(x))) - 0.69314718055994530942f;
}

// ---- f32x2 helpers (table build) ----
__device__ __forceinline__ void fma2(unsigned long long& d, unsigned long long a, unsigned long long b) {
    asm("fma.rn.f32x2 %0, %1, %2, %0;" : "+l"(d) : "l"(a), "l"(b));
}
__device__ __forceinline__ unsigned long long bcast2(float a) {
    unsigned long long r; asm("mov.b64 %0, {%1, %1};" : "=l"(r) : "f"(a)); return r;
}
__device__ __forceinline__ unsigned long long pack2(float a, float b) {
    unsigned long long r; asm("mov.b64 %0, {%1, %2};" : "=l"(r) : "f"(a), "f"(b)); return r;
}
__device__ __forceinline__ float2 unpack2(unsigned long long v) {
    float2 f; asm("mov.b64 {%0, %1}, %2;" : "=f"(f.x), "=f"(f.y) : "l"(v)); return f;
}

// ---- HMMA m16n8k16 ----
__device__ __forceinline__ void hmma16816(float& c0, float& c1, float& c2, float& c3,
                                          unsigned a0, unsigned a1, unsigned a2, unsigned a3,
                                          unsigned b0, unsigned b1) {
    asm volatile(
        "mma.sync.aligned.m16n8k16.row.col.f32.f16.f16.f32 "
        "{%0,%1,%2,%3}, {%4,%5,%6,%7}, {%8,%9}, {%0,%1,%2,%3};"
        : "+f"(c0), "+f"(c1), "+f"(c2), "+f"(c3)
        : "r"(a0), "r"(a1), "r"(a2), "r"(a3), "r"(b0), "r"(b1));
}

// Transpose+convert via smem tiles: dst[n][k] = (half)src[k][n].
// Tiles: L*3*16 square (128x128) + 8 for o1w (128x64). Also zeroes g_acc.
__global__ void __launch_bounds__(256) convert_weights(
    const float* __restrict__ w1, const float* __restrict__ w2,
    const float* __restrict__ w3, const float* __restrict__ o1w, int L)
{
    __shared__ float t[32][33];
    int tile = blockIdx.x;
    int tid = threadIdx.x;
    int r4 = tid >> 5, c = tid & 31;          // 8 rows x 32 cols per pass, 4 passes
    if (tile == 0 && tid < 64) g_acc[tid] = 0.f;

    const float* src; __half* dst;
    int k0, n0, srcStride, dstStride;
    int nsq = L * 48;
    if (tile < nsq) {
        int l = tile / 48, r = tile % 48;
        int m = r / 16, tt = r % 16;
        int tr = tt >> 2, tc = tt & 3;        // 4x4 tiles of 32
        src = (m == 0 ? w1 : m == 1 ? w2 : w3) + (size_t)l * H * H;
        dst = (m == 0 ? g_w1t : m == 1 ? g_w2t : g_w3t) + (size_t)l * H * H;
        k0 = tr * 32; n0 = tc * 32; srcStride = H; dstStride = H;
    } else {
        int tt = tile - nsq;                  // 8 tiles: 4 (k) x 2 (n)
        int tr = tt >> 1, tc = tt & 1;
        src = o1w; dst = g_o1t;
        k0 = tr * 32; n0 = tc * 32; srcStride = 64; dstStride = H;
    }
#pragma unroll
    for (int i = 0; i < 4; i++) {
        int rr = r4 + i * 8;
        t[rr][c] = src[(size_t)(k0 + rr) * srcStride + n0 + c];
    }
    __syncthreads();
#pragma unroll
    for (int i = 0; i < 4; i++) {
        int rr = r4 + i * 8;                  // output row (n), col (k) contiguous
        dst[(size_t)(n0 + rr) * dstStride + k0 + c] = __float2half(t[c][rr]);
    }
}

// ======================= CSR build =======================
__global__ void hist_kernel(const int* __restrict__ dst, int E) {
    int e = blockIdx.x * blockDim.x + threadIdx.x;
    if (e < E) g_rank[e] = atomicAdd(&g_rowptr[dst[e] + 1], 1);
}

__global__ void __launch_bounds__(1024) scan_kernel(int n) {
    __shared__ int buf[10240];
    __shared__ int wsum[32];
    int t = threadIdx.x;
    const int C = 10;
    for (int i = t; i < 10240; i += 1024) buf[i] = (i < n) ? g_rowptr[i] : 0;
    __syncthreads();
    int base = t * C;
    int s = 0;
#pragma unroll
    for (int i = 0; i < C; i++) s += buf[base + i];
    int lane = t & 31, w = t >> 5;
    int v = s;
#pragma unroll
    for (int off = 1; off < 32; off <<= 1) {
        int u = __shfl_up_sync(0xffffffffu, v, off);
        if (lane >= off) v += u;
    }
    if (lane == 31) wsum[w] = v;
    __syncthreads();
    if (w == 0) {
        int xv = wsum[lane];
#pragma unroll
        for (int off = 1; off < 32; off <<= 1) {
            int u = __shfl_up_sync(0xffffffffu, xv, off);
            if (lane >= off) xv += u;
        }
        wsum[lane] = xv;
    }
    __syncthreads();
    int run = v - s + (w > 0 ? wsum[w - 1] : 0);
#pragma unroll
    for (int i = 0; i < C; i++) { run += buf[base + i]; buf[base + i] = run; }
    __syncthreads();
    for (int i = t; i < n; i += 1024) g_rowptr[i] = buf[i];
}

__global__ void scatter_kernel(const int* __restrict__ src, const int* __restrict__ dst,
                               const float* __restrict__ dist, int E) {
    int e = blockIdx.x * blockDim.x + threadIdx.x;
    if (e < E) {
        int p = g_rowptr[dst[e]] + g_rank[e];
        g_csr[p] = make_int2(src[e], __float_as_int(dist[e]));
    }
}

// ======================= Filter tables: 16 bins/block, paired fma2 ====
__global__ void __launch_bounds__(128) table_all(
    const float* __restrict__ mw1, const float* __restrict__ mb1,
    const float* __restrict__ mw2, const float* __restrict__ mb2)
{
    __shared__ unsigned long long eas2[BPB / 2][G];
    __shared__ unsigned long long a_s2[BPB / 2][H];
    int f = threadIdx.x;
    int b0 = blockIdx.x * BPB;
    int l = blockIdx.y;
    const float* w1 = mw1 + (size_t)l * G * H;
    const float* b1 = mb1 + (size_t)l * H;
    const float* w2 = mw2 + (size_t)l * H * H;
    const float* b2 = mb2 + (size_t)l * H;
    __half* tab = g_tab + (size_t)l * (NBINS + 1) * H;
    const float spacing = CUTOFF_F / (G - 1);
    const float coeff = -0.5f / (spacing * spacing);
    const float binw = CUTOFF_F / NBINS;

    for (int i = f; i < (BPB / 2) * G; i += 128) {
        int p = i / G, g = i - p * G;
        float dA = (b0 + 2 * p) * binw;
        float dB = dA + binw;
        float xA = dA - g * spacing, xB = dB - g * spacing;
        eas2[p][g] = pack2(expf(coeff * xA * xA), expf(coeff * xB * xB));
    }
    __syncthreads();

    unsigned long long a2[BPB / 2];
    {
        unsigned long long bvv = bcast2(b1[f]);
#pragma unroll
        for (int p = 0; p < BPB / 2; p++) a2[p] = bvv;
    }
#pragma unroll 2
    for (int g = 0; g < G; g++) {
        unsigned long long wb = bcast2(w1[g * H + f]);
#pragma unroll
        for (int p = 0; p < BPB / 2; p++) fma2(a2[p], eas2[p][g], wb);
    }
#pragma unroll
    for (int p = 0; p < BPB / 2; p++) {
        float2 v = unpack2(a2[p]);
        a_s2[p][f] = pack2(sspf(v.x), sspf(v.y));
    }
    __syncthreads();

    unsigned long long acc[BPB / 2];
#pragma unroll
    for (int p = 0; p < BPB / 2; p++) acc[p] = 0ull;
#pragma unroll 4
    for (int j = 0; j < H; j++) {
        unsigned long long wb = bcast2(w2[j * H + f]);
#pragma unroll
        for (int p = 0; p < BPB / 2; p++) fma2(acc[p], a_s2[p][j], wb);
    }
    float b2v = b2[f];
#pragma unroll
    for (int p = 0; p < BPB / 2; p++) {
        float2 v = unpack2(acc[p]);
        int bA = b0 + 2 * p, bB = bA + 1;
        float cA = 0.5f * (cosf(bA * binw * (PI_F / CUTOFF_F)) + 1.f);
        float cB = 0.5f * (cosf(bB * binw * (PI_F / CUTOFF_F)) + 1.f);
        if (bA <= NBINS) tab[(size_t)bA * H + f] = __float2half((v.x + b2v) * cA);
        if (bB <= NBINS) tab[(size_t)bB * H + f] = __float2half((v.y + b2v) * cB);
    }
}

// ======================= HMMA common (32-row tiles) =======================
#define APAD 136

__device__ __forceinline__ void stage_Ah32(const __half* __restrict__ A, __half (*As)[APAD],
                                           int r0, int M, int tid) {
#pragma unroll
    for (int rep = 0; rep < 2; rep++) {
        int fl = tid + rep * 256;
        int row = fl >> 4, u4 = fl & 15;
        uint4 v = (r0 + row < M) ? *(const uint4*)&A[(size_t)(r0 + row) * H + u4 * 8]
                                 : make_uint4(0u, 0u, 0u, 0u);
        *(uint4*)&As[row][u4 * 8] = v;
    }
}

__device__ __forceinline__ void stage_W(const __half* __restrict__ Wt, __half (*Ws)[APAD], int tid) {
#pragma unroll
    for (int rep = 0; rep < 8; rep++) {
        int w = tid + rep * 256;
        int n = w >> 4, kg = w & 15;
        *(uint4*)&Ws[n][kg * 8] = *(const uint4*)&Wt[n * H + kg * 8];
    }
}

__device__ __forceinline__ void ldg_W(const __half* __restrict__ Wt, uint4 (&r)[8], int tid) {
#pragma unroll
    for (int rep = 0; rep < 8; rep++) {
        int w = tid + rep * 256;
        int n = w >> 4, kg = w & 15;
        r[rep] = *(const uint4*)&Wt[n * H + kg * 8];
    }
}
__device__ __forceinline__ void sts_W(const uint4 (&r)[8], __half (*Ws)[APAD], int tid) {
#pragma unroll
    for (int rep = 0; rep < 8; rep++) {
        int w = tid + rep * 256;
        int n = w >> 4, kg = w & 15;
        *(uint4*)&Ws[n][kg * 8] = r[rep];
    }
}

__device__ __forceinline__ void stage_W64(const __half* __restrict__ Wt, __half (*Ws)[APAD], int tid) {
#pragma unroll
    for (int rep = 0; rep < 4; rep++) {
        int w = tid + rep * 256;
        int n = w >> 4, kg = w & 15;
        *(uint4*)&Ws[n][kg * 8] = *(const uint4*)&Wt[n * H + kg * 8];
    }
}

__device__ __forceinline__ void hmma32(const __half (*As)[APAD], const __half (*Ws)[APAD],
                                       float (&acc)[4][4], int warp_m, int warp_n,
                                       int tm, int tk) {
#pragma unroll
    for (int kc = 0; kc < 8; kc++) {
        int k0 = kc * 16;
        int mrow = warp_m * 16 + tm;
        unsigned a0 = *(const unsigned*)&As[mrow][k0 + tk];
        unsigned a1 = *(const unsigned*)&As[mrow + 8][k0 + tk];
        unsigned a2 = *(const unsigned*)&As[mrow][k0 + 8 + tk];
        unsigned a3 = *(const unsigned*)&As[mrow + 8][k0 + 8 + tk];
#pragma unroll
        for (int nt = 0; nt < 4; nt++) {
            int n0 = warp_n * 32 + nt * 8;
            unsigned b0 = *(const unsigned*)&Ws[n0 + tm][k0 + tk];
            unsigned b1 = *(const unsigned*)&Ws[n0 + tm][k0 + 8 + tk];
            hmma16816(acc[nt][0], acc[nt][1], acc[nt][2], acc[nt][3], a0, a1, a2, a3, b0, b1);
        }
    }
}

__device__ __forceinline__ void zero4(float (&acc)[4][4]) {
#pragma unroll
    for (int nt = 0; nt < 4; nt++)
#pragma unroll
        for (int i = 0; i < 4; i++) acc[nt][i] = 0.f;
}

// layer 0: h = emb[x]; xf = h @ W1   (embed fused into staging)
__global__ void __launch_bounds__(256) gemm_xf0(const int* __restrict__ x,
                                                const float* __restrict__ emb,
                                                const __half* __restrict__ Wt,
                                                float* __restrict__ hout,
                                                __half* __restrict__ xfo, int M) {
    __shared__ __half As[32][APAD];
    __shared__ __half Ws[128][APAD];
    int tid = threadIdx.x;
    int warp = tid >> 5, lane = tid & 31;
    int warp_m = warp >> 2, warp_n = warp & 3;
    int tm = lane >> 2, tk = (lane & 3) * 2;
    int r0 = blockIdx.x * 32;
#pragma unroll
    for (int rep = 0; rep < 4; rep++) {
        int fl = tid + rep * 256;
        int row = fl >> 5, f4 = fl & 31;
        float4 v = make_float4(0.f, 0.f, 0.f, 0.f);
        if (r0 + row < M) {
            v = *(const float4*)&emb[(size_t)x[r0 + row] * H + f4 * 4];
            *(float4*)&hout[(size_t)(r0 + row) * H + f4 * 4] = v;
        }
        __half2* p = (__half2*)&As[row][f4 * 4];
        p[0] = __floats2half2_rn(v.x, v.y);
        p[1] = __floats2half2_rn(v.z, v.w);
    }
    stage_W(Wt, Ws, tid);
    __syncthreads();
    float acc[4][4];
    zero4(acc);
    hmma32(As, Ws, acc, warp_m, warp_n, tm, tk);
    int row1 = r0 + warp_m * 16 + tm;
    int row2 = row1 + 8;
#pragma unroll
    for (int nt = 0; nt < 4; nt++) {
        int col = warp_n * 32 + nt * 8 + tk;
        if (row1 < M) *(__half2*)&xfo[(size_t)row1 * H + col] = __floats2half2_rn(acc[nt][0], acc[nt][1]);
        if (row2 < M) *(__half2*)&xfo[(size_t)row2 * H + col] = __floats2half2_rn(acc[nt][2], acc[nt][3]);
    }
}

// ======================= Edge gather (nearest-bin table) ======
__global__ void edge_gather(const __half* __restrict__ tab, int N) {
    int warp = (blockIdx.x * blockDim.x + threadIdx.x) >> 5;
    int lane = threadIdx.x & 31;
    if (warp >= N) return;
    int beg = g_rowptr[warp], end = g_rowptr[warp + 1];
    float a0 = 0.f, a1 = 0.f, a2 = 0.f, a3 = 0.f;
#pragma unroll 4
    for (int i = beg; i < end; i++) {
        int2 sd = g_csr[i];
        float d = __int_as_float(sd.y);
        float u = d * ((float)NBINS / CUTOFF_F) + 0.5f;
        int i0 = min(max((int)u, 0), NBINS);
        uint2 tp = *(const uint2*)&tab[(size_t)i0 * H + lane * 4];
        uint2 xq = *(const uint2*)&g_xfh[(size_t)sd.x * H + lane * 4];
        float2 w0 = __half22float2(*(__half2*)&tp.x);
        float2 w1 = __half22float2(*(__half2*)&tp.y);
        float2 xa = __half22float2(*(__half2*)&xq.x);
        float2 xb = __half22float2(*(__half2*)&xq.y);
        a0 += xa.x * w0.x;
        a1 += xa.y * w0.y;
        a2 += xb.x * w1.x;
        a3 += xb.y * w1.y;
    }
    __half2* op = (__half2*)&g_aggh[(size_t)warp * H + lane * 4];
    op[0] = __floats2half2_rn(a0, a1);
    op[1] = __floats2half2_rn(a2, a3);
}

// h += ssp(aggh @ W2 + b2) @ W3 + b3;  then xf_next = h_new @ W1n
__global__ void __launch_bounds__(256) gemm_dualX(const __half* __restrict__ A,
                                                  const __half* __restrict__ W2t,
                                                  const float* __restrict__ b2,
                                                  const __half* __restrict__ W3t,
                                                  const float* __restrict__ b3,
                                                  float* __restrict__ hio,
                                                  const __half* __restrict__ W1n,
                                                  __half* __restrict__ xfo, int M) {
    __shared__ __half As[32][APAD];
    __shared__ __half Ws[128][APAD];
    int tid = threadIdx.x;
    int warp = tid >> 5, lane = tid & 31;
    int warp_m = warp >> 2, warp_n = warp & 3;
    int tm = lane >> 2, tk = (lane & 3) * 2;
    int r0 = blockIdx.x * 32;
    int lr1 = warp_m * 16 + tm, lr2 = lr1 + 8;
    int row1 = r0 + lr1, row2 = r0 + lr2;

    stage_Ah32(A, As, r0, M, tid);
    stage_W(W2t, Ws, tid);
    uint4 wreg[8];
    ldg_W(W3t, wreg, tid);
    __syncthreads();
    float acc[4][4];
    zero4(acc);
    hmma32(As, Ws, acc, warp_m, warp_n, tm, tk);
    __syncthreads();
#pragma unroll
    for (int nt = 0; nt < 4; nt++) {
        int col = warp_n * 32 + nt * 8 + tk;
        float2 bb = *(const float2*)&b2[col];
        *(__half2*)&As[lr1][col] = __floats2half2_rn(sspf(acc[nt][0] + bb.x), sspf(acc[nt][1] + bb.y));
        *(__half2*)&As[lr2][col] = __floats2half2_rn(sspf(acc[nt][2] + bb.x), sspf(acc[nt][3] + bb.y));
    }
    sts_W(wreg, Ws, tid);
    if (W1n) ldg_W(W1n, wreg, tid);
    __syncthreads();
    zero4(acc);
    hmma32(As, Ws, acc, warp_m, warp_n, tm, tk);
    __syncthreads();
#pragma unroll
    for (int nt = 0; nt < 4; nt++) {
        int col = warp_n * 32 + nt * 8 + tk;
        float2 bb = *(const float2*)&b3[col];
        float2 o1 = make_float2(0.f, 0.f), o2 = make_float2(0.f, 0.f);
        if (row1 < M) o1 = *(const float2*)&hio[(size_t)row1 * H + col];
        if (row2 < M) o2 = *(const float2*)&hio[(size_t)row2 * H + col];
        o1.x += acc[nt][0] + bb.x; o1.y += acc[nt][1] + bb.y;
        o2.x += acc[nt][2] + bb.x; o2.y += acc[nt][3] + bb.y;
        if (row1 < M) *(float2*)&hio[(size_t)row1 * H + col] = o1;
        if (row2 < M) *(float2*)&hio[(size_t)row2 * H + col] = o2;
        *(__half2*)&As[lr1][col] = __floats2half2_rn(o1.x, o1.y);
        *(__half2*)&As[lr2][col] = __floats2half2_rn(o2.x, o2.y);
    }
    if (W1n) {
        sts_W(wreg, Ws, tid);
        __syncthreads();
        zero4(acc);
        hmma32(As, Ws, acc, warp_m, warp_n, tm, tk);
#pragma unroll
        for (int nt = 0; nt < 4; nt++) {
            int col = warp_n * 32 + nt * 8 + tk;
            if (row1 < M) *(__half2*)&xfo[(size_t)row1 * H + col] = __floats2half2_rn(acc[nt][0], acc[nt][1]);
            if (row2 < M) *(__half2*)&xfo[(size_t)row2 * H + col] = __floats2half2_rn(acc[nt][2], acc[nt][3]);
        }
    }
}

// ======================= Readout: colsum of ssp(h @ o1w + b1) via HMMA ====
__global__ void __launch_bounds__(256) readout_h(const float* __restrict__ A,
                                                 const float* __restrict__ b1, int M) {
    __shared__ __half As[64][APAD];
    __shared__ __half Ws[64][APAD];
    __shared__ float scol[64];
    int tid = threadIdx.x;
    int warp = tid >> 5, lane = tid & 31;
    int warp_m = warp >> 2, warp_n = warp & 3;
    int tm = lane >> 2, tk = (lane & 3) * 2;
    int r0 = blockIdx.x * 64;
    if (tid < 64) scol[tid] = 0.f;
#pragma unroll
    for (int rep = 0; rep < 8; rep++) {
        int fl = tid + rep * 256;
        int row = fl >> 5, f4 = fl & 31;
        float4 v = (r0 + row < M) ? *(const float4*)&A[(size_t)(r0 + row) * H + f4 * 4]
                                  : make_float4(0.f, 0.f, 0.f, 0.f);
        __half2* p = (__half2*)&As[row][f4 * 4];
        p[0] = __floats2half2_rn(v.x, v.y);
        p[1] = __floats2half2_rn(v.z, v.w);
    }
    stage_W64(g_o1t, Ws, tid);
    __syncthreads();
    float acc[2][2][4];
#pragma unroll
    for (int m = 0; m < 2; m++)
#pragma unroll
        for (int nt = 0; nt < 2; nt++)
#pragma unroll
            for (int i = 0; i < 4; i++) acc[m][nt][i] = 0.f;
#pragma unroll
    for (int msub = 0; msub < 2; msub++) {
        int mrow = msub * 32 + warp_m * 16 + tm;
#pragma unroll
        for (int kc = 0; kc < 8; kc++) {
            int k0 = kc * 16;
            unsigned a0 = *(const unsigned*)&As[mrow][k0 + tk];
            unsigned a1 = *(const unsigned*)&As[mrow + 8][k0 + tk];
            unsigned a2 = *(const unsigned*)&As[mrow][k0 + 8 + tk];
            unsigned a3 = *(const unsigned*)&As[mrow + 8][k0 + 8 + tk];
#pragma unroll
            for (int nt = 0; nt < 2; nt++) {
                int n0 = warp_n * 16 + nt * 8;
                unsigned b0 = *(const unsigned*)&Ws[n0 + tm][k0 + tk];
                unsigned bq1 = *(const unsigned*)&Ws[n0 + tm][k0 + 8 + tk];
                hmma16816(acc[msub][nt][0], acc[msub][nt][1], acc[msub][nt][2], acc[msub][nt][3],
                          a0, a1, a2, a3, b0, bq1);
            }
        }
    }
    float cs[2][2] = {{0.f, 0.f}, {0.f, 0.f}};
#pragma unroll
    for (int msub = 0; msub < 2; msub++) {
        int row1 = r0 + msub * 32 + warp_m * 16 + tm;
        int row2 = row1 + 8;
#pragma unroll
        for (int nt = 0; nt < 2; nt++) {
            int col = warp_n * 16 + nt * 8 + tk;
            float2 bb = *(const float2*)&b1[col];
            if (row1 < M) {
                cs[nt][0] += sspf(acc[msub][nt][0] + bb.x);
                cs[nt][1] += sspf(acc[msub][nt][1] + bb.y);
            }
            if (row2 < M) {
                cs[nt][0] += sspf(acc[msub][nt][2] + bb.x);
                cs[nt][1] += sspf(acc[msub][nt][3] + bb.y);
            }
        }
    }
#pragma unroll
    for (int off = 16; off >= 4; off >>= 1) {
#pragma unroll
        for (int nt = 0; nt < 2; nt++) {
            cs[nt][0] += __shfl_down_sync(0xffffffffu, cs[nt][0], off);
            cs[nt][1] += __shfl_down_sync(0xffffffffu, cs[nt][1], off);
        }
    }
    if (lane < 4) {
#pragma unroll
        for (int nt = 0; nt < 2; nt++) {
            int col = warp_n * 16 + nt * 8 + lane * 2;
            atomicAdd(&scol[col], cs[nt][0]);
            atomicAdd(&scol[col + 1], cs[nt][1]);
        }
    }
    __syncthreads();
    if (tid < 64) atomicAdd(&g_acc[tid], scol[tid]);
}

__global__ void readout_final(const float* __restrict__ o2w, const float* __restrict__ o2b,
                              const float* __restrict__ rw, const float* __restrict__ rb,
                              float* __restrict__ out, int N) {
    __shared__ float v[64];
    int t = threadIdx.x;
    float a = (float)N * o2b[t];
#pragma unroll 8
    for (int j = 0; j < 64; j++) a += g_acc[j] * o2w[j * 64 + t];
    v[t] = a;
    __syncthreads();
    if (t < 12) {
        float r = rb[t];
#pragma unroll
        for (int j = 0; j < 64; j++) r += v[j] * rw[j * 12 + t];
        out[t] = r;
    }
}

extern "C" void kernel_launch(void* const* d_in, const int* in_sizes, int n_in,
                              void* d_out, int out_size) {
    const int*   x    = (const int*)d_in[0];
    const int*   ei   = (const int*)d_in[1];
    const float* dist = (const float*)d_in[2];
    const float* emb  = (const float*)d_in[3];
    const float* mw1  = (const float*)d_in[4];
    const float* mb1  = (const float*)d_in[5];
    const float* mw2  = (const float*)d_in[6];
    const float* mb2  = (const float*)d_in[7];
    const float* l1w  = (const float*)d_in[8];
    const float* l2w  = (const float*)d_in[9];
    const float* l2b  = (const float*)d_in[10];
    const float* lw   = (const float*)d_in[11];
    const float* lb   = (const float*)d_in[12];
    const float* o1w  = (const float*)d_in[13];
    const float* o1b  = (const float*)d_in[14];
    const float* o2w  = (const float*)d_in[15];
    const float* o2b  = (const float*)d_in[16];
    const float* rw   = (const float*)d_in[17];
    const float* rb   = (const float*)d_in[18];

    int N = in_sizes[0];
    int E = in_sizes[2];
    int L = in_sizes[4] / (G * H);

    int *prow;
    cudaGetSymbolAddress((void**)&prow, g_rowptr);
    float *ph;
    __half *pxfh, *paggh, *pw1t, *pw2t, *pw3t, *ptab;
    cudaGetSymbolAddress((void**)&ph, g_h);
    cudaGetSymbolAddress((void**)&pxfh, g_xfh);
    cudaGetSymbolAddress((void**)&paggh, g_aggh);
    cudaGetSymbolAddress((void**)&pw1t, g_w1t);
    cudaGetSymbolAddress((void**)&pw2t, g_w2t);
    cudaGetSymbolAddress((void**)&pw3t, g_w3t);
    cudaGetSymbolAddress((void**)&ptab, g_tab);

    const int* esrc = ei;
    const int* edst = ei + E;

    int nb32 = (N + 31) / 32;
    int nb64 = (N + 63) / 64;
    int nbE = (N + 7) / 8;

    cudaMemsetAsync(prow, 0, (N + 1) * sizeof(int));
    hist_kernel<<<(E + 255) / 256, 256>>>(edst, E);
    scan_kernel<<<1, 1024>>>(N + 1);
    scatter_kernel<<<(E + 255) / 256, 256>>>(esrc, edst, dist, E);
    convert_weights<<<L * 48 + 8, 256>>>(l1w, l2w, lw, o1w, L);
    gemm_xf0<<<nb32, 256>>>(x, emb, pw1t, ph, pxfh, N);
    dim3 tgrid((NBINS + 1 + BPB - 1) / BPB, L);
    table_all<<<tgrid, 128>>>(mw1, mb1, mw2, mb2);

    for (int l = 0; l < L; l++) {
        edge_gather<<<nbE, 256>>>(ptab + (size_t)l * (NBINS + 1) * H, N);
        const __half* w1n = (l + 1 < L) ? pw1t + (size_t)(l + 1) * H * H : nullptr;
        gemm_dualX<<<nb32, 256>>>(paggh, pw2t + (size_t)l * H * H, l2b + (size_t)l * H,
                                  pw3t + (size_t)l * H * H, lb + (size_t)l * H,
                                  ph, w1n, pxfh, N);
    }

    readout_h<<<nb64, 256>>>(ph, o1b, N);
    readout_final<<<1, 64>>>(o2w, o2b, rw, rb, (float*)d_out, N);
}